// round 1
// baseline (speedup 1.0000x reference)
#include <cuda_runtime.h>
#include <cuda_bf16.h>
#include <math.h>

// Problem constants
#define NNODES 200000
#define E 128
#define BB 4096
#define H 20
#define NEG 5

// Scratch (device globals, allocation-free)
__device__ float g_Wa1[E];
__device__ float g_Wa2[E];
__device__ float g_Wgw[E];
__device__ float g_pp[BB];   // per-batch pos loss
__device__ float g_pn[BB];   // per-batch neg loss sum

// ---------------------------------------------------------------------------
// K0: Wa1 = W @ a[:E], Wa2 = W @ a[E:], Wgw = W @ gw   (row-dot per thread)
// ---------------------------------------------------------------------------
__global__ void precompute_kernel(const float* __restrict__ W,
                                  const float* __restrict__ a,
                                  const float* __restrict__ gw) {
    int e = threadIdx.x;  // 128 threads
    float s1 = 0.f, s2 = 0.f, s3 = 0.f;
    const float* row = W + e * E;
    #pragma unroll 8
    for (int f = 0; f < E; f++) {
        float w = row[f];
        s1 = fmaf(w, a[f], s1);
        s2 = fmaf(w, a[E + f], s2);
        s3 = fmaf(w, gw[f], s3);
    }
    g_Wa1[e] = s1; g_Wa2[e] = s2; g_Wgw[e] = s3;
}

// ---------------------------------------------------------------------------
// K1: node_emb = relu(X @ W1 + b1) @ W2 + b2, weights cached in dynamic smem
// blockDim = 128, one row per iteration, grid-stride.
// ---------------------------------------------------------------------------
__global__ void node_emb_kernel(const float* __restrict__ nf,
                                const float* __restrict__ W1,
                                const float* __restrict__ b1,
                                const float* __restrict__ W2,
                                const float* __restrict__ b2,
                                float* __restrict__ emb) {
    extern __shared__ float sm[];
    float* sW1 = sm;            // 128*60
    float* sW2 = sm + 7680;     // 60*128
    float* sb1 = sm + 15360;    // 60
    float* sb2 = sm + 15420;    // 128
    float* sx  = sm + 15548;    // 128
    float* shp = sm + 15676;    // 120 (two partial halves)
    float* shh = sm + 15796;    // 60

    int tid = threadIdx.x;
    for (int i = tid; i < E * 60; i += 128) sW1[i] = W1[i];
    for (int i = tid; i < 60 * E; i += 128) sW2[i] = W2[i];
    if (tid < 60) sb1[tid] = b1[tid];
    sb2[tid] = b2[tid];
    __syncthreads();

    for (int row = blockIdx.x; row < NNODES; row += gridDim.x) {
        sx[tid] = nf[(size_t)row * E + tid];
        __syncthreads();

        // stage 1: h[j] = b1[j] + sum_k x[k]*W1[k][j], split k over two thread groups
        if (tid < 60) {
            float acc = 0.f;
            #pragma unroll 16
            for (int k = 0; k < 64; k++) acc = fmaf(sx[k], sW1[k * 60 + tid], acc);
            shp[tid] = acc;
        } else if (tid >= 64 && tid < 124) {
            int j = tid - 64;
            float acc = 0.f;
            #pragma unroll 16
            for (int k = 64; k < 128; k++) acc = fmaf(sx[k], sW1[k * 60 + j], acc);
            shp[60 + j] = acc;
        }
        __syncthreads();
        if (tid < 60) shh[tid] = fmaxf(shp[tid] + shp[60 + tid] + sb1[tid], 0.f);
        __syncthreads();

        // stage 2: emb[t] = b2[t] + sum_j h[j]*W2[j][t]
        float e = sb2[tid];
        #pragma unroll 15
        for (int j = 0; j < 60; j++) e = fmaf(shh[j], sW2[j * E + tid], e);
        emb[(size_t)row * E + tid] = e;
        __syncthreads();
    }
}

// ---------------------------------------------------------------------------
// Warp reduction helpers (128-length vectors in smem, one warp per task)
// ---------------------------------------------------------------------------
__device__ __forceinline__ float warpSum(float v) {
    #pragma unroll
    for (int o = 16; o > 0; o >>= 1) v += __shfl_xor_sync(0xffffffffu, v, o);
    return v;
}
__device__ __forceinline__ float wdot(const float* x, const float* y, int lane) {
    float s = x[lane] * y[lane];
    s = fmaf(x[lane + 32], y[lane + 32], s);
    s = fmaf(x[lane + 64], y[lane + 64], s);
    s = fmaf(x[lane + 96], y[lane + 96], s);
    return warpSum(s);
}
__device__ __forceinline__ float wdist(const float* x, const float* y, int lane) {
    float s = 0.f;
    #pragma unroll
    for (int q = 0; q < 4; q++) {
        float d = x[lane + 32 * q] - y[lane + 32 * q];
        s = fmaf(d, d, s);
    }
    return warpSum(s);
}

// ---------------------------------------------------------------------------
// K2: one block (128 threads) per batch element
// ---------------------------------------------------------------------------
__global__ void batch_kernel(const int* __restrict__ src, const int* __restrict__ dst,
                             const float* __restrict__ e_times,
                             const int* __restrict__ shn, const int* __restrict__ thn,
                             const float* __restrict__ s_h_times, const float* __restrict__ t_h_times,
                             const float* __restrict__ s_mask, const float* __restrict__ t_mask,
                             const int* __restrict__ nsrc, const int* __restrict__ ndst,
                             const float* __restrict__ delta_s, const float* __restrict__ delta_t,
                             const float* __restrict__ gb,
                             const float* __restrict__ emb,
                             float* __restrict__ out) {
    __shared__ float sp0[E], sp1[E];
    __shared__ float e_s[H][E], e_t[H][E];
    __shared__ float sn0[NEG][E], sn1[NEG][E];
    __shared__ float sWa1[E], sWa2[E], sWgw[E];
    __shared__ float r_small[24];
    __shared__ float hsS[H], hsT[H], paS[H], paT[H];
    __shared__ float naS[H][NEG], naT[H][NEG];
    __shared__ float ds_[H], dt_[H], attS[H], attT[H], smS[H], smT[H];
    __shared__ float u_s[E], u_t[E];
    __shared__ float scal[8];

    int b = blockIdx.x;
    int tid = threadIdx.x, warp = tid >> 5, lane = tid & 31;
    int si = src[b], di = dst[b];

    sp0[tid] = emb[(size_t)si * E + tid];
    sp1[tid] = emb[(size_t)di * E + tid];
    #pragma unroll 4
    for (int h = 0; h < H; h++) {
        e_s[h][tid] = emb[(size_t)shn[b * H + h] * E + tid];
        e_t[h][tid] = emb[(size_t)thn[b * H + h] * E + tid];
    }
    #pragma unroll
    for (int n = 0; n < NEG; n++) {
        sn1[n][tid] = emb[(size_t)ndst[b * NEG + n] * E + tid];
        sn0[n][tid] = emb[(size_t)nsrc[b * NEG + n] * E + tid];
    }
    sWa1[tid] = g_Wa1[tid]; sWa2[tid] = g_Wa2[tid]; sWgw[tid] = g_Wgw[tid];
    if (tid < H) {
        float et = e_times[b];
        ds_[tid] = fabsf(et - s_h_times[b * H + tid]);
        dt_[tid] = fabsf(et - t_h_times[b * H + tid]);
        smS[tid] = s_mask[b * H + tid];
        smT[tid] = t_mask[b * H + tid];
    }
    __syncthreads();

    // Phase A1: 24 small reductions
    for (int t = warp; t < 24; t += 4) {
        float r;
        if      (t == 0) r = wdot(sp0, sp1, lane);
        else if (t == 1) r = wdot(sp0, sWa1, lane);
        else if (t == 2) r = wdot(sp1, sWa1, lane);
        else if (t == 3) r = wdist(sp0, sp1, lane);
        else if (t < 9)  r = wdot(sp0, sn1[t - 4], lane);
        else if (t < 14) r = wdot(sp1, sn0[t - 9], lane);
        else if (t < 19) r = wdist(sp0, sn1[t - 14], lane);
        else             r = wdist(sp1, sn0[t - 19], lane);
        if (lane == 0) r_small[t] = r;
    }
    // Phase A2: history scores + p_alpha
    for (int t = warp; t < 80; t += 4) {
        float r;
        if      (t < 20) r = wdot(e_s[t], sWa2, lane);
        else if (t < 40) r = wdot(e_t[t - 20], sWa2, lane);
        else if (t < 60) r = wdist(e_s[t - 40], sp1, lane);
        else             r = wdist(e_t[t - 60], sp0, lane);
        if (lane == 0) {
            if      (t < 20) hsS[t] = r;
            else if (t < 40) hsT[t - 20] = r;
            else if (t < 60) paS[t - 40] = r;
            else             paT[t - 60] = r;
        }
    }
    // Phase A3: n_alpha (200 reductions)
    for (int t = warp; t < 200; t += 4) {
        int u = (t < 100) ? t : t - 100;
        int h = u / NEG, n = u - NEG * h;
        float r = (t < 100) ? wdist(e_s[h], sn1[n], lane) : wdist(e_t[h], sn0[n], lane);
        if (lane == 0) { if (t < 100) naS[h][n] = r; else naT[h][n] = r; }
    }
    __syncthreads();

    // mid: softmax attention (thread 0, tiny)
    if (tid == 0) {
        float sA = r_small[1], tA = r_small[2];
        float dsv = delta_s[si], dtv = delta_t[di];
        scal[0] = dsv; scal[1] = dtv;
        float sims[H], simt[H];
        float mxs = -1e30f, mxt = -1e30f;
        for (int h = 0; h < H; h++) {
            float xs = expf(-dsv * ds_[h]) * (sA + hsS[h]);
            float xt = expf(-dsv * dt_[h]) * (tA + hsT[h]);   // ref uses ds for both sims
            sims[h] = xs > 0.f ? xs : 0.2f * xs;
            simt[h] = xt > 0.f ? xt : 0.2f * xt;
            mxs = fmaxf(mxs, sims[h]); mxt = fmaxf(mxt, simt[h]);
        }
        float sus = 0.f, sut = 0.f;
        for (int h = 0; h < H; h++) {
            float es2 = expf(sims[h] - mxs), et2 = expf(simt[h] - mxt);
            attS[h] = es2; attT[h] = et2; sus += es2; sut += et2;
        }
        float is = 1.f / sus, it = 1.f / sut;
        for (int h = 0; h < H; h++) { attS[h] *= is; attT[h] *= it; }
    }
    __syncthreads();

    // u = sum_h (att*mask)_h * hist_emb_h
    {
        float us = 0.f, ut = 0.f;
        #pragma unroll 4
        for (int h = 0; h < H; h++) {
            us = fmaf(attS[h] * smS[h], e_s[h][tid], us);
            ut = fmaf(attT[h] * smT[h], e_t[h][tid], ut);
        }
        u_s[tid] = us; u_t[tid] = ut;
    }
    __syncthreads();
    if (warp == 0) { float r = wdot(u_s, sWgw, lane); if (lane == 0) scal[2] = r; }
    if (warp == 1) { float r = wdot(u_t, sWgw, lane); if (lane == 0) scal[3] = r; }
    __syncthreads();

    // tail: scalar loss math (thread 0)
    if (tid == 0) {
        float dsv = scal[0], dtv = scal[1];
        float mds = 0.f, mdt = 0.f;
        for (int h = 0; h < H; h++) { mds += ds_[h]; mdt += dt_[h]; }
        mds *= (1.f / H); mdt *= (1.f / H);
        float fs = expf(-dsv * mds), ft = expf(-dtv * mdt);
        float gbv = gb[0];
        float ls = tanhf(fs * scal[2] + gbv);
        float lt = tanhf(ft * scal[3] + gbv);
        float m = fmaxf(ls, lt);
        float egs = expf(ls - m), egt = expf(lt - m);
        float ga_s = egs / (egs + egt), ga_t = egt / (egs + egt);

        float ews[H], ewt[H];
        float psum_s = 0.f, psum_t = 0.f;
        for (int h = 0; h < H; h++) {
            ews[h] = expf(dsv * ds_[h]) * attS[h] * smS[h];
            ewt[h] = expf(dtv * dt_[h]) * attT[h] * smT[h];
            psum_s = fmaf(ews[h], paS[h], psum_s);
            psum_t = fmaf(ewt[h], paT[h], psum_t);
        }
        float plam = r_small[3] + ga_s * psum_s + ga_t * psum_t;
        float pos = fmaxf(r_small[0], 0.f);
        float pm1 = pos - 1.f;
        float pl = -logf(1.f / (1.f + expf(-plam)) + 1e-6f) * pm1 * pm1;

        float nsum = 0.f;
        #pragma unroll
        for (int n = 0; n < NEG; n++) {
            float as = 0.f, at = 0.f;
            for (int h = 0; h < H; h++) {
                as = fmaf(ews[h], naS[h][n], as);
                at = fmaf(ewt[h], naT[h][n], at);
            }
            float nls = r_small[14 + n] + ga_s * as;
            float nlt = r_small[19 + n] + ga_t * at;
            float negs = fmaxf(r_small[4 + n], 0.f);
            float negt = fmaxf(r_small[9 + n], 0.f);
            nsum += -logf(1.f / (1.f + expf(nls)) + 1e-6f) * negs * negs;
            nsum += -logf(1.f / (1.f + expf(nlt)) + 1e-6f) * negt * negt;
        }
        g_pp[b] = pl;
        g_pn[b] = nsum;
        out[1 + b] = pos;   // estimated_weights
    }
}

// ---------------------------------------------------------------------------
// K3: deterministic loss reduction
// ---------------------------------------------------------------------------
__global__ void loss_kernel(float* __restrict__ out) {
    __shared__ float s1[256], s2[256];
    int t = threadIdx.x;
    float a = 0.f, c = 0.f;
    for (int i = t; i < BB; i += 256) { a += g_pp[i]; c += g_pn[i]; }
    s1[t] = a; s2[t] = c;
    __syncthreads();
    for (int o = 128; o > 0; o >>= 1) {
        if (t < o) { s1[t] += s1[t + o]; s2[t] += s2[t + o]; }
        __syncthreads();
    }
    if (t == 0) out[0] = s1[0] / 4096.0f + s2[0] / (4096.0f * 5.0f);
}

// ---------------------------------------------------------------------------
extern "C" void kernel_launch(void* const* d_in, const int* in_sizes, int n_in,
                              void* d_out, int out_size) {
    const float* nf      = (const float*)d_in[0];
    const int*   src     = (const int*)  d_in[1];
    const int*   dst     = (const int*)  d_in[2];
    const float* etm     = (const float*)d_in[3];
    const int*   shn     = (const int*)  d_in[4];
    const int*   thn     = (const int*)  d_in[5];
    const float* shtimes = (const float*)d_in[6];
    const float* thtimes = (const float*)d_in[7];
    const float* smask   = (const float*)d_in[8];
    const float* tmask   = (const float*)d_in[9];
    const int*   nsrc    = (const int*)  d_in[10];
    const int*   ndst    = (const int*)  d_in[11];
    const float* W1      = (const float*)d_in[12];
    const float* b1      = (const float*)d_in[13];
    const float* W2      = (const float*)d_in[14];
    const float* b2      = (const float*)d_in[15];
    const float* W       = (const float*)d_in[16];
    const float* a       = (const float*)d_in[17];
    const float* dsp     = (const float*)d_in[18];
    const float* dtp     = (const float*)d_in[19];
    const float* gw      = (const float*)d_in[20];
    const float* gb      = (const float*)d_in[21];

    float* out = (float*)d_out;
    float* emb = out + 1 + BB;   // node_emb lives directly in the output buffer

    precompute_kernel<<<1, 128>>>(W, a, gw);

    cudaFuncSetAttribute(node_emb_kernel,
                         cudaFuncAttributeMaxDynamicSharedMemorySize, 65536);
    node_emb_kernel<<<444, 128, 63424>>>(nf, W1, b1, W2, b2, emb);

    batch_kernel<<<BB, 128>>>(src, dst, etm, shn, thn, shtimes, thtimes,
                              smask, tmask, nsrc, ndst, dsp, dtp, gb, emb, out);

    loss_kernel<<<1, 256>>>(out);
}

// round 2
// speedup vs baseline: 2.1654x; 2.1654x over previous
#include <cuda_runtime.h>
#include <cuda_bf16.h>
#include <math.h>

// Problem constants
#define NNODES 200000
#define E 128
#define BB 4096
#define H 20
#define NEG 5
#define TR 16          // rows per MLP tile

// Scratch (device globals, allocation-free)
__device__ float g_Wa1[E];
__device__ float g_Wa2[E];
__device__ float g_Wgw[E];
__device__ float g_pp[BB];
__device__ float g_pn[BB];
__device__ float g_H[(size_t)NNODES * 64];   // hidden layer, padded 60->64

__device__ __forceinline__ float warpSum(float v) {
    #pragma unroll
    for (int o = 16; o > 0; o >>= 1) v += __shfl_xor_sync(0xffffffffu, v, o);
    return v;
}

// ---------------------------------------------------------------------------
// K0: Wa1 = W @ a[:E], Wa2 = W @ a[E:], Wgw = W @ gw  (warp-per-row, coalesced)
// ---------------------------------------------------------------------------
__global__ void precompute_kernel(const float* __restrict__ W,
                                  const float* __restrict__ a,
                                  const float* __restrict__ gw) {
    int warp = threadIdx.x >> 5, lane = threadIdx.x & 31;
    for (int row = warp; row < E; row += 4) {
        const float* wr = W + row * E;
        float s1 = 0.f, s2 = 0.f, s3 = 0.f;
        #pragma unroll
        for (int i = 0; i < 4; i++) {
            float wv = wr[lane + 32 * i];
            s1 = fmaf(wv, a[lane + 32 * i], s1);
            s2 = fmaf(wv, a[E + lane + 32 * i], s2);
            s3 = fmaf(wv, gw[lane + 32 * i], s3);
        }
        s1 = warpSum(s1); s2 = warpSum(s2); s3 = warpSum(s3);
        if (lane == 0) { g_Wa1[row] = s1; g_Wa2[row] = s2; g_Wgw[row] = s3; }
    }
}

// ---------------------------------------------------------------------------
// K1a: H = relu(X @ W1 + b1)   [200000 x 128] @ [128 x 60] -> padded [.. x 64]
// 128 threads = 2 k-halves x 64 hidden cols. W1 slice in registers.
// ---------------------------------------------------------------------------
__global__ void __launch_bounds__(128)
mlp1_kernel(const float* __restrict__ nf, const float* __restrict__ W1,
            const float* __restrict__ b1, float* __restrict__ Hout) {
    __shared__ float xs[TR * 128];
    __shared__ float ps[TR * 64];
    int tid = threadIdx.x;
    int g = tid >> 6;         // k-half: 0 -> k[0:64), 1 -> k[64:128)
    int j = tid & 63;         // hidden col (padded)

    float w[64];
    #pragma unroll
    for (int kk = 0; kk < 64; kk++)
        w[kk] = (j < 60) ? W1[(64 * g + kk) * 60 + j] : 0.f;
    float bj = (j < 60) ? b1[j] : 0.f;

    for (int tile = blockIdx.x; tile < NNODES / TR; tile += gridDim.x) {
        size_t base = (size_t)tile * TR;
        const float4* src = (const float4*)(nf + base * 128);
        float4* dstv = (float4*)xs;
        #pragma unroll
        for (int i = 0; i < 4; i++) dstv[tid + 128 * i] = src[tid + 128 * i];
        __syncthreads();

        float acc[TR];
        #pragma unroll
        for (int r = 0; r < TR; r++) acc[r] = 0.f;

        #pragma unroll
        for (int q = 0; q < 16; q++) {
            #pragma unroll
            for (int r = 0; r < TR; r++) {
                float4 xq = *(const float4*)&xs[r * 128 + 64 * g + 4 * q];
                acc[r] = fmaf(xq.x, w[4 * q + 0], acc[r]);
                acc[r] = fmaf(xq.y, w[4 * q + 1], acc[r]);
                acc[r] = fmaf(xq.z, w[4 * q + 2], acc[r]);
                acc[r] = fmaf(xq.w, w[4 * q + 3], acc[r]);
            }
        }

        if (g == 1) {
            #pragma unroll
            for (int r = 0; r < TR; r++) ps[r * 64 + j] = acc[r];
        }
        __syncthreads();
        if (g == 0) {
            #pragma unroll
            for (int r = 0; r < TR; r++)
                Hout[(base + r) * 64 + j] = fmaxf(acc[r] + ps[r * 64 + j] + bj, 0.f);
        }
        __syncthreads();
    }
}

// ---------------------------------------------------------------------------
// K1b: emb = H @ W2 + b2   [200000 x 60] @ [60 x 128]
// 128 threads = 128 output cols. W2 column in registers. Dual accumulators.
// ---------------------------------------------------------------------------
__global__ void __launch_bounds__(128)
mlp2_kernel(const float* __restrict__ Hin, const float* __restrict__ W2,
            const float* __restrict__ b2, float* __restrict__ emb) {
    __shared__ float hs[TR * 64];
    int t = threadIdx.x;

    float w[60];
    #pragma unroll
    for (int jj = 0; jj < 60; jj++) w[jj] = W2[jj * 128 + t];
    float bt = b2[t];

    for (int tile = blockIdx.x; tile < NNODES / TR; tile += gridDim.x) {
        size_t base = (size_t)tile * TR;
        const float4* src = (const float4*)(Hin + base * 64);
        float4* dstv = (float4*)hs;
        dstv[t] = src[t];
        dstv[t + 128] = src[t + 128];
        __syncthreads();

        for (int r = 0; r < TR; r++) {
            float a0 = bt, a1 = 0.f;
            #pragma unroll
            for (int q = 0; q < 15; q++) {
                float4 hq = *(const float4*)&hs[r * 64 + 4 * q];
                if (q & 1) {
                    a1 = fmaf(hq.x, w[4 * q + 0], a1);
                    a1 = fmaf(hq.y, w[4 * q + 1], a1);
                    a1 = fmaf(hq.z, w[4 * q + 2], a1);
                    a1 = fmaf(hq.w, w[4 * q + 3], a1);
                } else {
                    a0 = fmaf(hq.x, w[4 * q + 0], a0);
                    a0 = fmaf(hq.y, w[4 * q + 1], a0);
                    a0 = fmaf(hq.z, w[4 * q + 2], a0);
                    a0 = fmaf(hq.w, w[4 * q + 3], a0);
                }
            }
            emb[(base + r) * 128 + t] = a0 + a1;
        }
        __syncthreads();
    }
}

// ---------------------------------------------------------------------------
// Warp reduction helpers over 128-length smem vectors
// ---------------------------------------------------------------------------
__device__ __forceinline__ float wdot(const float* x, const float* y, int lane) {
    float s = x[lane] * y[lane];
    s = fmaf(x[lane + 32], y[lane + 32], s);
    s = fmaf(x[lane + 64], y[lane + 64], s);
    s = fmaf(x[lane + 96], y[lane + 96], s);
    return warpSum(s);
}
__device__ __forceinline__ float wdist(const float* x, const float* y, int lane) {
    float s = 0.f;
    #pragma unroll
    for (int q = 0; q < 4; q++) {
        float d = x[lane + 32 * q] - y[lane + 32 * q];
        s = fmaf(d, d, s);
    }
    return warpSum(s);
}

// ---------------------------------------------------------------------------
// K2: one block (128 threads) per batch element
// ---------------------------------------------------------------------------
__global__ void batch_kernel(const int* __restrict__ src, const int* __restrict__ dst,
                             const float* __restrict__ e_times,
                             const int* __restrict__ shn, const int* __restrict__ thn,
                             const float* __restrict__ s_h_times, const float* __restrict__ t_h_times,
                             const float* __restrict__ s_mask, const float* __restrict__ t_mask,
                             const int* __restrict__ nsrc, const int* __restrict__ ndst,
                             const float* __restrict__ delta_s, const float* __restrict__ delta_t,
                             const float* __restrict__ gb,
                             const float* __restrict__ emb,
                             float* __restrict__ out) {
    __shared__ float sp0[E], sp1[E];
    __shared__ float e_s[H][E], e_t[H][E];
    __shared__ float sn0[NEG][E], sn1[NEG][E];
    __shared__ float sWa1[E], sWa2[E], sWgw[E];
    __shared__ float r_small[24];
    __shared__ float hsS[H], hsT[H], paS[H], paT[H];
    __shared__ float naS[H][NEG], naT[H][NEG];
    __shared__ float ds_[H], dt_[H], attS[H], attT[H], smS[H], smT[H];
    __shared__ float u_s[E], u_t[E];
    __shared__ float scal[8];

    int b = blockIdx.x;
    int tid = threadIdx.x, warp = tid >> 5, lane = tid & 31;
    int si = src[b], di = dst[b];

    sp0[tid] = emb[(size_t)si * E + tid];
    sp1[tid] = emb[(size_t)di * E + tid];
    #pragma unroll 4
    for (int h = 0; h < H; h++) {
        e_s[h][tid] = emb[(size_t)shn[b * H + h] * E + tid];
        e_t[h][tid] = emb[(size_t)thn[b * H + h] * E + tid];
    }
    #pragma unroll
    for (int n = 0; n < NEG; n++) {
        sn1[n][tid] = emb[(size_t)ndst[b * NEG + n] * E + tid];
        sn0[n][tid] = emb[(size_t)nsrc[b * NEG + n] * E + tid];
    }
    sWa1[tid] = g_Wa1[tid]; sWa2[tid] = g_Wa2[tid]; sWgw[tid] = g_Wgw[tid];
    if (tid < H) {
        float et = e_times[b];
        ds_[tid] = fabsf(et - s_h_times[b * H + tid]);
        dt_[tid] = fabsf(et - t_h_times[b * H + tid]);
        smS[tid] = s_mask[b * H + tid];
        smT[tid] = t_mask[b * H + tid];
    }
    __syncthreads();

    // Phase A1: 24 small reductions
    for (int t = warp; t < 24; t += 4) {
        float r;
        if      (t == 0) r = wdot(sp0, sp1, lane);
        else if (t == 1) r = wdot(sp0, sWa1, lane);
        else if (t == 2) r = wdot(sp1, sWa1, lane);
        else if (t == 3) r = wdist(sp0, sp1, lane);
        else if (t < 9)  r = wdot(sp0, sn1[t - 4], lane);
        else if (t < 14) r = wdot(sp1, sn0[t - 9], lane);
        else if (t < 19) r = wdist(sp0, sn1[t - 14], lane);
        else             r = wdist(sp1, sn0[t - 19], lane);
        if (lane == 0) r_small[t] = r;
    }
    // Phase A2: history scores + p_alpha
    for (int t = warp; t < 80; t += 4) {
        float r;
        if      (t < 20) r = wdot(e_s[t], sWa2, lane);
        else if (t < 40) r = wdot(e_t[t - 20], sWa2, lane);
        else if (t < 60) r = wdist(e_s[t - 40], sp1, lane);
        else             r = wdist(e_t[t - 60], sp0, lane);
        if (lane == 0) {
            if      (t < 20) hsS[t] = r;
            else if (t < 40) hsT[t - 20] = r;
            else if (t < 60) paS[t - 40] = r;
            else             paT[t - 60] = r;
        }
    }
    // Phase A3: n_alpha (200 reductions)
    for (int t = warp; t < 200; t += 4) {
        int u = (t < 100) ? t : t - 100;
        int h = u / NEG, n = u - NEG * h;
        float r = (t < 100) ? wdist(e_s[h], sn1[n], lane) : wdist(e_t[h], sn0[n], lane);
        if (lane == 0) { if (t < 100) naS[h][n] = r; else naT[h][n] = r; }
    }
    __syncthreads();

    // mid: softmax attention (thread 0, tiny)
    if (tid == 0) {
        float sA = r_small[1], tA = r_small[2];
        float dsv = delta_s[si], dtv = delta_t[di];
        scal[0] = dsv; scal[1] = dtv;
        float sims[H], simt[H];
        float mxs = -1e30f, mxt = -1e30f;
        for (int h = 0; h < H; h++) {
            float xs = expf(-dsv * ds_[h]) * (sA + hsS[h]);
            float xt = expf(-dsv * dt_[h]) * (tA + hsT[h]);   // ref uses ds for both sims
            sims[h] = xs > 0.f ? xs : 0.2f * xs;
            simt[h] = xt > 0.f ? xt : 0.2f * xt;
            mxs = fmaxf(mxs, sims[h]); mxt = fmaxf(mxt, simt[h]);
        }
        float sus = 0.f, sut = 0.f;
        for (int h = 0; h < H; h++) {
            float es2 = expf(sims[h] - mxs), et2 = expf(simt[h] - mxt);
            attS[h] = es2; attT[h] = et2; sus += es2; sut += et2;
        }
        float is = 1.f / sus, it = 1.f / sut;
        for (int h = 0; h < H; h++) { attS[h] *= is; attT[h] *= it; }
    }
    __syncthreads();

    // u = sum_h (att*mask)_h * hist_emb_h
    {
        float us = 0.f, ut = 0.f;
        #pragma unroll 4
        for (int h = 0; h < H; h++) {
            us = fmaf(attS[h] * smS[h], e_s[h][tid], us);
            ut = fmaf(attT[h] * smT[h], e_t[h][tid], ut);
        }
        u_s[tid] = us; u_t[tid] = ut;
    }
    __syncthreads();
    if (warp == 0) { float r = wdot(u_s, sWgw, lane); if (lane == 0) scal[2] = r; }
    if (warp == 1) { float r = wdot(u_t, sWgw, lane); if (lane == 0) scal[3] = r; }
    __syncthreads();

    // tail: scalar loss math (thread 0)
    if (tid == 0) {
        float dsv = scal[0], dtv = scal[1];
        float mds = 0.f, mdt = 0.f;
        for (int h = 0; h < H; h++) { mds += ds_[h]; mdt += dt_[h]; }
        mds *= (1.f / H); mdt *= (1.f / H);
        float fs = expf(-dsv * mds), ft = expf(-dtv * mdt);
        float gbv = gb[0];
        float ls = tanhf(fs * scal[2] + gbv);
        float lt = tanhf(ft * scal[3] + gbv);
        float m = fmaxf(ls, lt);
        float egs = expf(ls - m), egt = expf(lt - m);
        float ga_s = egs / (egs + egt), ga_t = egt / (egs + egt);

        float ews[H], ewt[H];
        float psum_s = 0.f, psum_t = 0.f;
        for (int h = 0; h < H; h++) {
            ews[h] = expf(dsv * ds_[h]) * attS[h] * smS[h];
            ewt[h] = expf(dtv * dt_[h]) * attT[h] * smT[h];
            psum_s = fmaf(ews[h], paS[h], psum_s);
            psum_t = fmaf(ewt[h], paT[h], psum_t);
        }
        float plam = r_small[3] + ga_s * psum_s + ga_t * psum_t;
        float pos = fmaxf(r_small[0], 0.f);
        float pm1 = pos - 1.f;
        float pl = -logf(1.f / (1.f + expf(-plam)) + 1e-6f) * pm1 * pm1;

        float nsum = 0.f;
        #pragma unroll
        for (int n = 0; n < NEG; n++) {
            float as = 0.f, at = 0.f;
            for (int h = 0; h < H; h++) {
                as = fmaf(ews[h], naS[h][n], as);
                at = fmaf(ewt[h], naT[h][n], at);
            }
            float nls = r_small[14 + n] + ga_s * as;
            float nlt = r_small[19 + n] + ga_t * at;
            float negs = fmaxf(r_small[4 + n], 0.f);
            float negt = fmaxf(r_small[9 + n], 0.f);
            nsum += -logf(1.f / (1.f + expf(nls)) + 1e-6f) * negs * negs;
            nsum += -logf(1.f / (1.f + expf(nlt)) + 1e-6f) * negt * negt;
        }
        g_pp[b] = pl;
        g_pn[b] = nsum;
        out[1 + b] = pos;   // estimated_weights
    }
}

// ---------------------------------------------------------------------------
// K3: deterministic loss reduction (vectorized)
// ---------------------------------------------------------------------------
__global__ void loss_kernel(float* __restrict__ out) {
    __shared__ float s1[256], s2[256];
    int t = threadIdx.x;
    float a = 0.f, c = 0.f;
    const float4* p1 = (const float4*)g_pp;
    const float4* p2 = (const float4*)g_pn;
    for (int i = t; i < BB / 4; i += 256) {
        float4 v = p1[i]; a += (v.x + v.y) + (v.z + v.w);
        float4 u = p2[i]; c += (u.x + u.y) + (u.z + u.w);
    }
    s1[t] = a; s2[t] = c;
    __syncthreads();
    for (int o = 128; o > 0; o >>= 1) {
        if (t < o) { s1[t] += s1[t + o]; s2[t] += s2[t + o]; }
        __syncthreads();
    }
    if (t == 0) out[0] = s1[0] / 4096.0f + s2[0] / (4096.0f * 5.0f);
}

// ---------------------------------------------------------------------------
extern "C" void kernel_launch(void* const* d_in, const int* in_sizes, int n_in,
                              void* d_out, int out_size) {
    const float* nf      = (const float*)d_in[0];
    const int*   src     = (const int*)  d_in[1];
    const int*   dst     = (const int*)  d_in[2];
    const float* etm     = (const float*)d_in[3];
    const int*   shn     = (const int*)  d_in[4];
    const int*   thn     = (const int*)  d_in[5];
    const float* shtimes = (const float*)d_in[6];
    const float* thtimes = (const float*)d_in[7];
    const float* smask   = (const float*)d_in[8];
    const float* tmask   = (const float*)d_in[9];
    const int*   nsrc    = (const int*)  d_in[10];
    const int*   ndst    = (const int*)  d_in[11];
    const float* W1      = (const float*)d_in[12];
    const float* b1      = (const float*)d_in[13];
    const float* W2      = (const float*)d_in[14];
    const float* b2      = (const float*)d_in[15];
    const float* W       = (const float*)d_in[16];
    const float* a       = (const float*)d_in[17];
    const float* dsp     = (const float*)d_in[18];
    const float* dtp     = (const float*)d_in[19];
    const float* gw      = (const float*)d_in[20];
    const float* gb      = (const float*)d_in[21];

    float* out = (float*)d_out;
    float* emb = out + 1 + BB;   // node_emb lives directly in the output buffer

    float* Hbuf;
    cudaGetSymbolAddress((void**)&Hbuf, g_H);

    precompute_kernel<<<1, 128>>>(W, a, gw);
    mlp1_kernel<<<740, 128>>>(nf, W1, b1, Hbuf);
    mlp2_kernel<<<1036, 128>>>(Hbuf, W2, b2, emb);
    batch_kernel<<<BB, 128>>>(src, dst, etm, shn, thn, shtimes, thtimes,
                              smask, tmask, nsrc, ndst, dsp, dtp, gb, emb, out);
    loss_kernel<<<1, 256>>>(out);
}

// round 4
// speedup vs baseline: 2.2654x; 1.0462x over previous
#include <cuda_runtime.h>
#include <cuda_bf16.h>
#include <math.h>

// Problem constants
#define NNODES 200000
#define E 128
#define BB 4096
#define H 20
#define NEG 5
#define TR 16          // rows per MLP tile
#define NTASK 348      // 345 dot tasks padded to 87 quads
#define NVEC 55

// Scratch (device globals, allocation-free)
__device__ __align__(16) float g_Wa1[E];
__device__ __align__(16) float g_Wa2[E];
__device__ __align__(16) float g_Wgw[E];
__device__ float g_pp[BB];
__device__ float g_pn[BB];
__device__ __align__(16) float g_H[(size_t)NNODES * 64];    // hidden, padded 60->64
__device__ __align__(16) float g_emb[(size_t)NNODES * E];   // aligned emb copy
__device__ __align__(8)  unsigned short g_tasks[NTASK];

// ---------------------------------------------------------------------------
// f32x2 packed helpers (Blackwell)
// ---------------------------------------------------------------------------
__device__ __forceinline__ unsigned long long mul2(unsigned long long a, unsigned long long b) {
    unsigned long long d;
    asm("mul.rn.f32x2 %0, %1, %2;" : "=l"(d) : "l"(a), "l"(b));
    return d;
}
__device__ __forceinline__ unsigned long long fma2(unsigned long long a, unsigned long long b,
                                                   unsigned long long c) {
    unsigned long long d;
    asm("fma.rn.f32x2 %0, %1, %2, %3;" : "=l"(d) : "l"(a), "l"(b), "l"(c));
    return d;
}
__device__ __forceinline__ float hadd2(unsigned long long v) {
    float lo = __uint_as_float((unsigned)(v & 0xffffffffull));
    float hi = __uint_as_float((unsigned)(v >> 32));
    return lo + hi;
}
__device__ __forceinline__ unsigned long long packf2(float lo, float hi) {
    return (unsigned long long)__float_as_uint(lo) |
           ((unsigned long long)__float_as_uint(hi) << 32);
}

union F4U2 {
    float4 f4;
    struct { unsigned long long lo, hi; } u;
};

__device__ __forceinline__ float warpSum(float v) {
    #pragma unroll
    for (int o = 16; o > 0; o >>= 1) v += __shfl_xor_sync(0xffffffffu, v, o);
    return v;
}
__device__ __forceinline__ float warpMax(float v) {
    #pragma unroll
    for (int o = 16; o > 0; o >>= 1) v = fmaxf(v, __shfl_xor_sync(0xffffffffu, v, o));
    return v;
}

// ---------------------------------------------------------------------------
// Dot task table. Vector ids:
// 0:p0 1:p1 2:Wa1 3:Wa2 4:Wgw 5..9:nd 10..14:ns 15..34:e_s 35..54:e_t
// Dot results layout:
// 0: p0.p1 | 1: p0.Wa1 | 2: p1.Wa1 | 3..7: p0.nd | 8..12: p1.ns
// 13..32: e_s.Wa2 | 33..52: e_t.Wa2 | 53..72: e_s.p1 | 73..92: e_t.p0
// 93..192: e_s[h].nd[n] | 193..292: e_t[h].ns[n]
// 293:|p0|^2 294:|p1|^2 295..299:|nd|^2 300..304:|ns|^2
// 305..324:|e_s|^2 325..344:|e_t|^2 | 345..347: pad
// ---------------------------------------------------------------------------
__device__ void taskDecode(int i, int& l, int& r) {
    if      (i == 0)  { l = 0; r = 1; }
    else if (i == 1)  { l = 0; r = 2; }
    else if (i == 2)  { l = 1; r = 2; }
    else if (i < 8)   { l = 0; r = 5 + (i - 3); }
    else if (i < 13)  { l = 1; r = 10 + (i - 8); }
    else if (i < 33)  { l = 15 + (i - 13); r = 3; }
    else if (i < 53)  { l = 35 + (i - 33); r = 3; }
    else if (i < 73)  { l = 15 + (i - 53); r = 1; }
    else if (i < 93)  { l = 35 + (i - 73); r = 0; }
    else if (i < 193) { int u = i - 93;  l = 15 + u / 5; r = 5 + u % 5; }
    else if (i < 293) { int u = i - 193; l = 35 + u / 5; r = 10 + u % 5; }
    else if (i == 293){ l = 0; r = 0; }
    else if (i == 294){ l = 1; r = 1; }
    else if (i < 300) { l = 5 + (i - 295); r = l; }
    else if (i < 305) { l = 10 + (i - 300); r = l; }
    else if (i < 325) { l = 15 + (i - 305); r = l; }
    else if (i < 345) { l = 35 + (i - 325); r = l; }
    else              { l = 0; r = 0; }
}

// ---------------------------------------------------------------------------
// K0: Wa1/Wa2/Wgw matvecs + build dot-task table
// ---------------------------------------------------------------------------
__global__ void precompute_kernel(const float* __restrict__ W,
                                  const float* __restrict__ a,
                                  const float* __restrict__ gw) {
    int tid = threadIdx.x;
    int warp = tid >> 5, lane = tid & 31;
    for (int row = warp; row < E; row += 4) {
        const float* wr = W + row * E;
        float s1 = 0.f, s2 = 0.f, s3 = 0.f;
        #pragma unroll
        for (int i = 0; i < 4; i++) {
            float wv = wr[lane + 32 * i];
            s1 = fmaf(wv, a[lane + 32 * i], s1);
            s2 = fmaf(wv, a[E + lane + 32 * i], s2);
            s3 = fmaf(wv, gw[lane + 32 * i], s3);
        }
        s1 = warpSum(s1); s2 = warpSum(s2); s3 = warpSum(s3);
        if (lane == 0) { g_Wa1[row] = s1; g_Wa2[row] = s2; g_Wgw[row] = s3; }
    }
    for (int i = tid; i < NTASK; i += 128) {
        int l, r;
        taskDecode(i, l, r);
        g_tasks[i] = (unsigned short)((l << 8) | r);
    }
}

// ---------------------------------------------------------------------------
// K1a: H = relu(X @ W1 + b1) using packed f32x2 FMAs
// ---------------------------------------------------------------------------
__global__ void __launch_bounds__(128)
mlp1_kernel(const float* __restrict__ nf, const float* __restrict__ W1,
            const float* __restrict__ b1, float* __restrict__ Hout) {
    __shared__ float4 xs4[TR * 32];
    __shared__ float ps[TR * 64];
    int tid = threadIdx.x;
    int g = tid >> 6;         // k-half
    int j = tid & 63;         // hidden col (padded)

    unsigned long long w2[32];
    #pragma unroll
    for (int kk = 0; kk < 32; kk++) {
        float wa = (j < 60) ? W1[(64 * g + 2 * kk) * 60 + j] : 0.f;
        float wb = (j < 60) ? W1[(64 * g + 2 * kk + 1) * 60 + j] : 0.f;
        w2[kk] = packf2(wa, wb);
    }
    float bj = (j < 60) ? b1[j] : 0.f;

    for (int tile = blockIdx.x; tile < NNODES / TR; tile += gridDim.x) {
        size_t base = (size_t)tile * TR;
        const float4* src = (const float4*)(nf + base * 128);
        #pragma unroll
        for (int i = 0; i < 4; i++) xs4[tid + 128 * i] = src[tid + 128 * i];
        __syncthreads();

        unsigned long long acc[TR];
        #pragma unroll
        for (int r = 0; r < TR; r++) acc[r] = 0ull;

        #pragma unroll
        for (int q = 0; q < 16; q++) {
            #pragma unroll
            for (int r = 0; r < TR; r++) {
                F4U2 xq; xq.f4 = xs4[r * 32 + 16 * g + q];
                acc[r] = fma2(xq.u.lo, w2[2 * q], acc[r]);
                acc[r] = fma2(xq.u.hi, w2[2 * q + 1], acc[r]);
            }
        }

        if (g == 1) {
            #pragma unroll
            for (int r = 0; r < TR; r++) ps[r * 64 + j] = hadd2(acc[r]);
        }
        __syncthreads();
        if (g == 0) {
            #pragma unroll
            for (int r = 0; r < TR; r++)
                Hout[(base + r) * 64 + j] = fmaxf(hadd2(acc[r]) + ps[r * 64 + j] + bj, 0.f);
        }
        __syncthreads();
    }
}

// ---------------------------------------------------------------------------
// K1b: emb = H @ W2 + b2 using packed f32x2 FMAs.
// Dual-store: aligned scratch g_emb (for batch gather) + output region.
// ---------------------------------------------------------------------------
__global__ void __launch_bounds__(128)
mlp2_kernel(const float* __restrict__ Hin, const float* __restrict__ W2,
            const float* __restrict__ b2, float* __restrict__ emb_out,
            float* __restrict__ emb_al) {
    __shared__ float4 hs4[TR * 16];
    int t = threadIdx.x;

    unsigned long long w2[30];
    #pragma unroll
    for (int jj = 0; jj < 30; jj++)
        w2[jj] = packf2(W2[(2 * jj) * 128 + t], W2[(2 * jj + 1) * 128 + t]);
    float bt = b2[t];

    for (int tile = blockIdx.x; tile < NNODES / TR; tile += gridDim.x) {
        size_t base = (size_t)tile * TR;
        const float4* src = (const float4*)(Hin + base * 64);
        hs4[t] = src[t];
        hs4[t + 128] = src[t + 128];
        __syncthreads();

        for (int r = 0; r < TR; r++) {
            unsigned long long a0 = 0ull, a1 = 0ull;
            #pragma unroll
            for (int q = 0; q < 15; q++) {
                F4U2 hq; hq.f4 = hs4[r * 16 + q];
                if (q & 1) {
                    a1 = fma2(hq.u.lo, w2[2 * q], a1);
                    a1 = fma2(hq.u.hi, w2[2 * q + 1], a1);
                } else {
                    a0 = fma2(hq.u.lo, w2[2 * q], a0);
                    a0 = fma2(hq.u.hi, w2[2 * q + 1], a0);
                }
            }
            float v = bt + hadd2(a0) + hadd2(a1);
            emb_out[(base + r) * 128 + t] = v;
            emb_al[(base + r) * 128 + t] = v;
        }
        __syncthreads();
    }
}

// ---------------------------------------------------------------------------
// K2: one block (128 threads) per batch element — dot-engine version
// ---------------------------------------------------------------------------
__global__ void __launch_bounds__(128)
batch_kernel(const int* __restrict__ src, const int* __restrict__ dst,
             const float* __restrict__ e_times,
             const int* __restrict__ shn, const int* __restrict__ thn,
             const float* __restrict__ s_h_times, const float* __restrict__ t_h_times,
             const float* __restrict__ s_mask, const float* __restrict__ t_mask,
             const int* __restrict__ nsrc, const int* __restrict__ ndst,
             const float* __restrict__ delta_s, const float* __restrict__ delta_t,
             const float* __restrict__ gb,
             const float* __restrict__ emb,
             float* __restrict__ out) {
    __shared__ float4 vecs[NVEC][32];
    __shared__ float dotres[NTASK];
    __shared__ float ds_[H], dt_[H], smS[H], smT[H];
    __shared__ float attmS[H], attmT[H];
    __shared__ alignas(16) float u_s[E];
    __shared__ alignas(16) float u_t[E];
    __shared__ float BnS[NEG], BnT[NEG];
    __shared__ float scal[12];

    int b = blockIdx.x;
    int tid = threadIdx.x, warp = tid >> 5, lane = tid & 31;
    int si = src[b], di = dst[b];

    // gather all 55 vectors (float4 per lane, one warp per vector)
    for (int v = warp; v < NVEC; v += 4) {
        const float* s;
        if      (v == 0) s = emb + (size_t)si * E;
        else if (v == 1) s = emb + (size_t)di * E;
        else if (v == 2) s = g_Wa1;
        else if (v == 3) s = g_Wa2;
        else if (v == 4) s = g_Wgw;
        else if (v < 10) s = emb + (size_t)ndst[b * NEG + (v - 5)] * E;
        else if (v < 15) s = emb + (size_t)nsrc[b * NEG + (v - 10)] * E;
        else if (v < 35) s = emb + (size_t)shn[b * H + (v - 15)] * E;
        else             s = emb + (size_t)thn[b * H + (v - 35)] * E;
        vecs[v][lane] = ((const float4*)s)[lane];
    }
    if (tid < H) {
        float et = e_times[b];
        ds_[tid] = fabsf(et - s_h_times[b * H + tid]);
        dt_[tid] = fabsf(et - t_h_times[b * H + tid]);
        smS[tid] = s_mask[b * H + tid];
        smT[tid] = t_mask[b * H + tid];
    }
    __syncthreads();

    // dot engine: 87 quads, 4 dots each, quad-reduce (6 shuffles / 4 dots)
    const float4* vt = &vecs[0][0];
    for (int q = warp; q < NTASK / 4; q += 4) {
        ushort4 t4 = ((const ushort4*)g_tasks)[q];
        float p[4];
        unsigned short tt[4] = {t4.x, t4.y, t4.z, t4.w};
        #pragma unroll
        for (int k = 0; k < 4; k++) {
            int l = tt[k] >> 8, r = tt[k] & 255;
            F4U2 A, B;
            A.f4 = vt[l * 32 + lane];
            B.f4 = vt[r * 32 + lane];
            unsigned long long pr = mul2(A.u.lo, B.u.lo);
            pr = fma2(A.u.hi, B.u.hi, pr);
            p[k] = hadd2(pr);
        }
        // quad reduce
        unsigned m = 0xffffffffu;
        bool h16 = (lane & 16) != 0;
        float snd = h16 ? p[0] : p[1];
        float rcv = __shfl_xor_sync(m, snd, 16);
        float x = (h16 ? p[1] : p[0]) + rcv;
        snd = h16 ? p[2] : p[3];
        rcv = __shfl_xor_sync(m, snd, 16);
        float y = (h16 ? p[3] : p[2]) + rcv;
        bool h8 = (lane & 8) != 0;
        snd = h8 ? x : y;
        rcv = __shfl_xor_sync(m, snd, 8);
        float z = (h8 ? y : x) + rcv;
        z += __shfl_xor_sync(m, z, 4);
        z += __shfl_xor_sync(m, z, 2);
        z += __shfl_xor_sync(m, z, 1);
        // lanes 0->p0, 8->p2, 16->p1, 24->p3
        if ((lane & 7) == 0) {
            int grp = lane >> 3;
            int off = (grp == 1) ? 2 : (grp == 2) ? 1 : (grp == 3) ? 3 : 0;
            dotres[q * 4 + off] = z;
        }
    }
    __syncthreads();

    // side warps: 0 = S, 1 = T. lane = history index h
    if (warp < 2) {
        int side = warp;
        int h = lane;
        bool act = h < H;
        float dsv = delta_s[si];
        float dtv = delta_t[di];
        float dh = act ? (side ? dt_[h] : ds_[h]) : 0.f;
        float nsh = act ? dotres[(side ? 325 : 305) + h] : 0.f;
        float score = (side ? dotres[2] : dotres[1]) +
                      (act ? dotres[(side ? 33 : 13) + h] : 0.f);
        float sim;
        if (act) {
            float xv = expf(-dsv * dh) * score;       // both sides use dsv (ref)
            sim = xv > 0.f ? xv : 0.2f * xv;
        } else sim = -1e30f;
        float mx = warpMax(sim);
        float ex = act ? expf(sim - mx) : 0.f;
        float sume = warpSum(ex);
        float att = ex / sume;
        float mask = act ? (side ? smT[h] : smS[h]) : 0.f;
        if (act) (side ? attmT : attmS)[h] = att * mask;
        float deltaX = side ? dtv : dsv;
        float ew = act ? expf(deltaX * dh) * att * mask : 0.f;
        float pa = act ? (nsh + dotres[side ? 293 : 294] -
                          2.f * dotres[(side ? 73 : 53) + h]) : 0.f;
        float psum = warpSum(ew * pa);
        float A = warpSum(ew);
        float md = warpSum(act ? dh : 0.f) * (1.f / H);
        #pragma unroll
        for (int n = 0; n < NEG; n++) {
            float dhn = act ? dotres[(side ? 193 : 93) + h * NEG + n] : 0.f;
            float Dn = warpSum(ew * (nsh - 2.f * dhn));
            if (lane == 0) (side ? BnT : BnS)[n] = Dn;
        }
        if (lane == 0) {
            scal[4 + side] = psum;
            scal[6 + side] = A;
            scal[8 + side] = md;
            scal[0 + side] = side ? dtv : dsv;
        }
    }
    __syncthreads();

    // u = sum_h (att*mask)_h * hist_emb_h, all 128 threads
    {
        const float* smvf = (const float*)vecs;
        float us = 0.f, ut = 0.f;
        #pragma unroll 4
        for (int h = 0; h < H; h++) {
            us = fmaf(attmS[h], smvf[(15 + h) * E + tid], us);
            ut = fmaf(attmT[h], smvf[(35 + h) * E + tid], ut);
        }
        u_s[tid] = us; u_t[tid] = ut;
    }
    __syncthreads();
    if (warp < 2) {
        const float4* uv = (const float4*)(warp ? u_t : u_s);
        F4U2 A, B;
        A.f4 = uv[lane];
        B.f4 = vecs[4][lane];
        unsigned long long pr = mul2(A.u.lo, B.u.lo);
        pr = fma2(A.u.hi, B.u.hi, pr);
        float r = warpSum(hadd2(pr));
        if (lane == 0) scal[2 + warp] = r;
    }
    __syncthreads();

    // final scalar tail
    if (tid == 0) {
        float dsv = scal[0], dtv = scal[1];
        float fs = expf(-dsv * scal[8]);
        float ft = expf(-dtv * scal[9]);
        float gbv = gb[0];
        float ls = tanhf(fs * scal[2] + gbv);
        float lt = tanhf(ft * scal[3] + gbv);
        float mm = fmaxf(ls, lt);
        float egs = expf(ls - mm), egt = expf(lt - mm);
        float inv = 1.f / (egs + egt);
        float ga_s = egs * inv, ga_t = egt * inv;

        float np0 = dotres[293], np1 = dotres[294];
        float p_mu = np0 + np1 - 2.f * dotres[0];
        float plam = p_mu + ga_s * scal[4] + ga_t * scal[5];
        float pos = fmaxf(dotres[0], 0.f);
        float pm1 = pos - 1.f;
        float pl = -logf(1.f / (1.f + expf(-plam)) + 1e-6f) * pm1 * pm1;

        float A_S = scal[6], A_T = scal[7];
        float nsum = 0.f;
        #pragma unroll
        for (int n = 0; n < NEG; n++) {
            float nnd = dotres[295 + n], nns = dotres[300 + n];
            float asn = BnS[n] + nnd * A_S;
            float atn = BnT[n] + nns * A_T;
            float nls = (np0 + nnd - 2.f * dotres[3 + n]) + ga_s * asn;
            float nlt = (np1 + nns - 2.f * dotres[8 + n]) + ga_t * atn;
            float negs = fmaxf(dotres[3 + n], 0.f);
            float negt = fmaxf(dotres[8 + n], 0.f);
            nsum += -logf(1.f / (1.f + expf(nls)) + 1e-6f) * negs * negs;
            nsum += -logf(1.f / (1.f + expf(nlt)) + 1e-6f) * negt * negt;
        }
        g_pp[b] = pl;
        g_pn[b] = nsum;
        out[1 + b] = pos;
    }
}

// ---------------------------------------------------------------------------
// K3: deterministic loss reduction
// ---------------------------------------------------------------------------
__global__ void loss_kernel(float* __restrict__ out) {
    __shared__ float s1[256], s2[256];
    int t = threadIdx.x;
    float a = 0.f, c = 0.f;
    const float4* p1 = (const float4*)g_pp;
    const float4* p2 = (const float4*)g_pn;
    for (int i = t; i < BB / 4; i += 256) {
        float4 v = p1[i]; a += (v.x + v.y) + (v.z + v.w);
        float4 u = p2[i]; c += (u.x + u.y) + (u.z + u.w);
    }
    s1[t] = a; s2[t] = c;
    __syncthreads();
    for (int o = 128; o > 0; o >>= 1) {
        if (t < o) { s1[t] += s1[t + o]; s2[t] += s2[t + o]; }
        __syncthreads();
    }
    if (t == 0) out[0] = s1[0] / 4096.0f + s2[0] / (4096.0f * 5.0f);
}

// ---------------------------------------------------------------------------
extern "C" void kernel_launch(void* const* d_in, const int* in_sizes, int n_in,
                              void* d_out, int out_size) {
    const float* nf      = (const float*)d_in[0];
    const int*   src     = (const int*)  d_in[1];
    const int*   dst     = (const int*)  d_in[2];
    const float* etm     = (const float*)d_in[3];
    const int*   shn     = (const int*)  d_in[4];
    const int*   thn     = (const int*)  d_in[5];
    const float* shtimes = (const float*)d_in[6];
    const float* thtimes = (const float*)d_in[7];
    const float* smask   = (const float*)d_in[8];
    const float* tmask   = (const float*)d_in[9];
    const int*   nsrc    = (const int*)  d_in[10];
    const int*   ndst    = (const int*)  d_in[11];
    const float* W1      = (const float*)d_in[12];
    const float* b1      = (const float*)d_in[13];
    const float* W2      = (const float*)d_in[14];
    const float* b2      = (const float*)d_in[15];
    const float* W       = (const float*)d_in[16];
    const float* a       = (const float*)d_in[17];
    const float* dsp     = (const float*)d_in[18];
    const float* dtp     = (const float*)d_in[19];
    const float* gw      = (const float*)d_in[20];
    const float* gb      = (const float*)d_in[21];

    float* out = (float*)d_out;
    float* emb_out = out + 1 + BB;   // node_emb output region (4B-aligned only!)

    float* Hbuf;  cudaGetSymbolAddress((void**)&Hbuf, g_H);
    float* Ebuf;  cudaGetSymbolAddress((void**)&Ebuf, g_emb);

    precompute_kernel<<<1, 128>>>(W, a, gw);
    mlp1_kernel<<<740, 128>>>(nf, W1, b1, Hbuf);
    mlp2_kernel<<<1036, 128>>>(Hbuf, W2, b2, emb_out, Ebuf);
    batch_kernel<<<BB, 128>>>(src, dst, etm, shn, thn, shtimes, thtimes,
                              smask, tmask, nsrc, ndst, dsp, dtp, gb, Ebuf, out);
    loss_kernel<<<1, 256>>>(out);
}

// round 6
// speedup vs baseline: 2.6161x; 1.1548x over previous
#include <cuda_runtime.h>
#include <cuda_bf16.h>
#include <math.h>

// Problem constants
#define NNODES 200000
#define E 128
#define BB 4096
#define H 20
#define NEG 5
#define TR 16          // rows per mlp1 tile
#define TR2 32         // rows per mlp2 tile
#define NTASK 124      // 105 phase1 + 3 pad + 14 phase2 + 2 pad = 31 quads
#define NVEC 55        // gathered vectors
#define NVEC2 59       // + u_s, u_t, v_s, v_t

// Scratch (device globals, allocation-free)
__device__ __align__(16) float g_Wa1[E];
__device__ __align__(16) float g_Wa2[E];
__device__ __align__(16) float g_Wgw[E];
__device__ float g_pp[BB];
__device__ float g_pn[BB];
__device__ __align__(16) float g_H[(size_t)NNODES * 64];    // hidden, padded 60->64
__device__ __align__(16) float g_emb[(size_t)NNODES * E];   // aligned emb copy
__device__ __align__(8)  unsigned short g_tasks[NTASK];

// ---------------------------------------------------------------------------
// f32x2 packed helpers (Blackwell)
// ---------------------------------------------------------------------------
__device__ __forceinline__ unsigned long long mul2(unsigned long long a, unsigned long long b) {
    unsigned long long d;
    asm("mul.rn.f32x2 %0, %1, %2;" : "=l"(d) : "l"(a), "l"(b));
    return d;
}
__device__ __forceinline__ unsigned long long fma2(unsigned long long a, unsigned long long b,
                                                   unsigned long long c) {
    unsigned long long d;
    asm("fma.rn.f32x2 %0, %1, %2, %3;" : "=l"(d) : "l"(a), "l"(b), "l"(c));
    return d;
}
__device__ __forceinline__ float hadd2(unsigned long long v) {
    float lo = __uint_as_float((unsigned)(v & 0xffffffffull));
    float hi = __uint_as_float((unsigned)(v >> 32));
    return lo + hi;
}
__device__ __forceinline__ unsigned long long packf2(float lo, float hi) {
    return (unsigned long long)__float_as_uint(lo) |
           ((unsigned long long)__float_as_uint(hi) << 32);
}

union F4U2 {
    float4 f4;
    struct { unsigned long long lo, hi; } u;
};

__device__ __forceinline__ float warpSum(float v) {
    #pragma unroll
    for (int o = 16; o > 0; o >>= 1) v += __shfl_xor_sync(0xffffffffu, v, o);
    return v;
}
__device__ __forceinline__ float warpMax(float v) {
    #pragma unroll
    for (int o = 16; o > 0; o >>= 1) v = fmaxf(v, __shfl_xor_sync(0xffffffffu, v, o));
    return v;
}

// cp.async helpers
__device__ __forceinline__ unsigned smaddr(const void* p) {
    return (unsigned)__cvta_generic_to_shared(p);
}
#define CPASYNC16(dst, src) \
    asm volatile("cp.async.cg.shared.global [%0], [%1], 16;" :: "r"(dst), "l"(src))
#define CPCOMMIT() asm volatile("cp.async.commit_group;")
#define CPWAIT(n)  asm volatile("cp.async.wait_group %0;" :: "n"(n))

// ---------------------------------------------------------------------------
// Task table. Vector ids:
// 0:p0 1:p1 2:Wa1 3:Wa2 4:Wgw 5..9:nd 10..14:ns 15..34:e_s 35..54:e_t
// 55:u_s 56:u_t 57:v_s 58:v_t
// Phase-1 results (0..107):
// 0: p0.p1 | 1: p0.Wa1 | 2: p1.Wa1 | 3..7: p0.nd | 8..12: p1.ns
// 13..32: e_s.Wa2 | 33..52: e_t.Wa2 | 53:|p0|^2 54:|p1|^2
// 55..59:|nd|^2 60..64:|ns|^2 | 65..84:|e_s|^2 | 85..104:|e_t|^2 | 105..107 pad
// Phase-2 results (108..123):
// 108: u_s.Wgw | 109: u_t.Wgw | 110: v_s.p1 | 111: v_t.p0
// 112..116: v_s.nd | 117..121: v_t.ns | 122,123 pad
// ---------------------------------------------------------------------------
__device__ void taskDecode(int i, int& l, int& r) {
    if      (i == 0)  { l = 0; r = 1; }
    else if (i == 1)  { l = 0; r = 2; }
    else if (i == 2)  { l = 1; r = 2; }
    else if (i < 8)   { l = 0; r = 5 + (i - 3); }
    else if (i < 13)  { l = 1; r = 10 + (i - 8); }
    else if (i < 33)  { l = 15 + (i - 13); r = 3; }
    else if (i < 53)  { l = 35 + (i - 33); r = 3; }
    else if (i == 53) { l = 0; r = 0; }
    else if (i == 54) { l = 1; r = 1; }
    else if (i < 60)  { l = 5 + (i - 55); r = l; }
    else if (i < 65)  { l = 10 + (i - 60); r = l; }
    else if (i < 85)  { l = 15 + (i - 65); r = l; }
    else if (i < 105) { l = 35 + (i - 85); r = l; }
    else if (i < 108) { l = 0; r = 0; }
    else if (i == 108){ l = 55; r = 4; }
    else if (i == 109){ l = 56; r = 4; }
    else if (i == 110){ l = 57; r = 1; }
    else if (i == 111){ l = 58; r = 0; }
    else if (i < 117) { l = 57; r = 5 + (i - 112); }
    else if (i < 122) { l = 58; r = 10 + (i - 117); }
    else              { l = 0; r = 0; }
}

// ---------------------------------------------------------------------------
// K0: Wa1/Wa2/Wgw matvecs + build dot-task table
// ---------------------------------------------------------------------------
__global__ void precompute_kernel(const float* __restrict__ W,
                                  const float* __restrict__ a,
                                  const float* __restrict__ gw) {
    int tid = threadIdx.x;
    int warp = tid >> 5, lane = tid & 31;
    for (int row = warp; row < E; row += 4) {
        const float* wr = W + row * E;
        float s1 = 0.f, s2 = 0.f, s3 = 0.f;
        #pragma unroll
        for (int i = 0; i < 4; i++) {
            float wv = wr[lane + 32 * i];
            s1 = fmaf(wv, a[lane + 32 * i], s1);
            s2 = fmaf(wv, a[E + lane + 32 * i], s2);
            s3 = fmaf(wv, gw[lane + 32 * i], s3);
        }
        s1 = warpSum(s1); s2 = warpSum(s2); s3 = warpSum(s3);
        if (lane == 0) { g_Wa1[row] = s1; g_Wa2[row] = s2; g_Wgw[row] = s3; }
    }
    for (int i = tid; i < NTASK; i += 128) {
        int l, r;
        taskDecode(i, l, r);
        g_tasks[i] = (unsigned short)((l << 8) | r);
    }
}

// ---------------------------------------------------------------------------
// K1a: H = relu(X @ W1 + b1), double-buffered cp.async tiles, f32x2 FMAs
// ---------------------------------------------------------------------------
__global__ void __launch_bounds__(128)
mlp1_kernel(const float* __restrict__ nf, const float* __restrict__ W1,
            const float* __restrict__ b1, float* __restrict__ Hout) {
    __shared__ float4 xs4[2][TR * 32];
    __shared__ float ps[TR * 64];
    int tid = threadIdx.x;
    int g = tid >> 6;         // k-half
    int j = tid & 63;         // hidden col (padded)

    unsigned long long w2[32];
    #pragma unroll
    for (int kk = 0; kk < 32; kk++) {
        float wa = (j < 60) ? W1[(64 * g + 2 * kk) * 60 + j] : 0.f;
        float wb = (j < 60) ? W1[(64 * g + 2 * kk + 1) * 60 + j] : 0.f;
        w2[kk] = packf2(wa, wb);
    }
    float bj = (j < 60) ? b1[j] : 0.f;

    const int NT = NNODES / TR;
    int tile = blockIdx.x, stride = gridDim.x;

    if (tile < NT) {
        const float4* src = (const float4*)(nf + (size_t)tile * TR * 128);
        #pragma unroll
        for (int i = 0; i < 4; i++)
            CPASYNC16(smaddr(&xs4[0][tid + 128 * i]), src + tid + 128 * i);
    }
    CPCOMMIT();

    int buf = 0;
    for (; tile < NT; tile += stride, buf ^= 1) {
        int nxt = tile + stride;
        if (nxt < NT) {
            const float4* src = (const float4*)(nf + (size_t)nxt * TR * 128);
            #pragma unroll
            for (int i = 0; i < 4; i++)
                CPASYNC16(smaddr(&xs4[buf ^ 1][tid + 128 * i]), src + tid + 128 * i);
            CPCOMMIT();
            CPWAIT(1);
        } else {
            CPCOMMIT();
            CPWAIT(0);
        }
        __syncthreads();

        unsigned long long acc[TR];
        #pragma unroll
        for (int r = 0; r < TR; r++) acc[r] = 0ull;

        #pragma unroll
        for (int q = 0; q < 16; q++) {
            #pragma unroll
            for (int r = 0; r < TR; r++) {
                F4U2 xq; xq.f4 = xs4[buf][r * 32 + 16 * g + q];
                acc[r] = fma2(xq.u.lo, w2[2 * q], acc[r]);
                acc[r] = fma2(xq.u.hi, w2[2 * q + 1], acc[r]);
            }
        }

        if (g == 1) {
            #pragma unroll
            for (int r = 0; r < TR; r++) ps[r * 64 + j] = hadd2(acc[r]);
        }
        __syncthreads();
        if (g == 0) {
            size_t base = (size_t)tile * TR;
            #pragma unroll
            for (int r = 0; r < TR; r++)
                Hout[(base + r) * 64 + j] = fmaxf(hadd2(acc[r]) + ps[r * 64 + j] + bj, 0.f);
        }
        __syncthreads();
    }
}

// ---------------------------------------------------------------------------
// K1b: emb = H @ W2 + b2, double-buffered cp.async, dual store
// ---------------------------------------------------------------------------
__global__ void __launch_bounds__(128)
mlp2_kernel(const float* __restrict__ Hin, const float* __restrict__ W2,
            const float* __restrict__ b2, float* __restrict__ emb_out,
            float* __restrict__ emb_al) {
    __shared__ float4 hs4[2][TR2 * 16];
    int t = threadIdx.x;

    unsigned long long w2[30];
    #pragma unroll
    for (int jj = 0; jj < 30; jj++)
        w2[jj] = packf2(W2[(2 * jj) * 128 + t], W2[(2 * jj + 1) * 128 + t]);
    float bt = b2[t];

    const int NT = NNODES / TR2;
    int tile = blockIdx.x, stride = gridDim.x;

    if (tile < NT) {
        const float4* src = (const float4*)(Hin + (size_t)tile * TR2 * 64);
        #pragma unroll
        for (int i = 0; i < 4; i++)
            CPASYNC16(smaddr(&hs4[0][t + 128 * i]), src + t + 128 * i);
    }
    CPCOMMIT();

    int buf = 0;
    for (; tile < NT; tile += stride, buf ^= 1) {
        int nxt = tile + stride;
        if (nxt < NT) {
            const float4* src = (const float4*)(Hin + (size_t)nxt * TR2 * 64);
            #pragma unroll
            for (int i = 0; i < 4; i++)
                CPASYNC16(smaddr(&hs4[buf ^ 1][t + 128 * i]), src + t + 128 * i);
            CPCOMMIT();
            CPWAIT(1);
        } else {
            CPCOMMIT();
            CPWAIT(0);
        }
        __syncthreads();

        size_t base = (size_t)tile * TR2;
        for (int r = 0; r < TR2; r++) {
            unsigned long long a0 = 0ull, a1 = 0ull;
            #pragma unroll
            for (int q = 0; q < 15; q++) {
                F4U2 hq; hq.f4 = hs4[buf][r * 16 + q];
                if (q & 1) {
                    a1 = fma2(hq.u.lo, w2[2 * q], a1);
                    a1 = fma2(hq.u.hi, w2[2 * q + 1], a1);
                } else {
                    a0 = fma2(hq.u.lo, w2[2 * q], a0);
                    a0 = fma2(hq.u.hi, w2[2 * q + 1], a0);
                }
            }
            float v = bt + hadd2(a0) + hadd2(a1);
            emb_out[(base + r) * 128 + t] = v;
            emb_al[(base + r) * 128 + t] = v;
        }
        __syncthreads();
    }
}

// ---------------------------------------------------------------------------
// K2: one block (128 threads) per batch element — collapsed dot engine
// ---------------------------------------------------------------------------
__global__ void __launch_bounds__(128)
batch_kernel(const int* __restrict__ src, const int* __restrict__ dst,
             const float* __restrict__ e_times,
             const int* __restrict__ shn, const int* __restrict__ thn,
             const float* __restrict__ s_h_times, const float* __restrict__ t_h_times,
             const float* __restrict__ s_mask, const float* __restrict__ t_mask,
             const int* __restrict__ nsrc, const int* __restrict__ ndst,
             const float* __restrict__ delta_s, const float* __restrict__ delta_t,
             const float* __restrict__ gb,
             const float* __restrict__ emb,
             float* __restrict__ out) {
    __shared__ float4 vecs[NVEC2][32];
    __shared__ float dotres[NTASK];
    __shared__ float ds_[H], dt_[H], smS[H], smT[H];
    __shared__ float attmS[H], attmT[H], ewS[H], ewT[H];
    __shared__ float scal[12];

    int b = blockIdx.x;
    int tid = threadIdx.x, warp = tid >> 5, lane = tid & 31;
    int si = src[b], di = dst[b];

    // gather 55 vectors (float4 per lane, one warp per vector)
    for (int v = warp; v < NVEC; v += 4) {
        const float* s;
        if      (v == 0) s = emb + (size_t)si * E;
        else if (v == 1) s = emb + (size_t)di * E;
        else if (v == 2) s = g_Wa1;
        else if (v == 3) s = g_Wa2;
        else if (v == 4) s = g_Wgw;
        else if (v < 10) s = emb + (size_t)ndst[b * NEG + (v - 5)] * E;
        else if (v < 15) s = emb + (size_t)nsrc[b * NEG + (v - 10)] * E;
        else if (v < 35) s = emb + (size_t)shn[b * H + (v - 15)] * E;
        else             s = emb + (size_t)thn[b * H + (v - 35)] * E;
        vecs[v][lane] = ((const float4*)s)[lane];
    }
    if (tid < H) {
        float et = e_times[b];
        ds_[tid] = fabsf(et - s_h_times[b * H + tid]);
        dt_[tid] = fabsf(et - t_h_times[b * H + tid]);
        smS[tid] = s_mask[b * H + tid];
        smT[tid] = t_mask[b * H + tid];
    }
    __syncthreads();

    const float4* vt = &vecs[0][0];
    unsigned m = 0xffffffffu;

    // phase-1 dots: quads 0..26
    for (int q = warp; q < 27; q += 4) {
        ushort4 t4 = ((const ushort4*)g_tasks)[q];
        float p[4];
        unsigned short tt[4] = {t4.x, t4.y, t4.z, t4.w};
        #pragma unroll
        for (int k = 0; k < 4; k++) {
            int l = tt[k] >> 8, r = tt[k] & 255;
            F4U2 A, B;
            A.f4 = vt[l * 32 + lane];
            B.f4 = vt[r * 32 + lane];
            unsigned long long pr = mul2(A.u.lo, B.u.lo);
            pr = fma2(A.u.hi, B.u.hi, pr);
            p[k] = hadd2(pr);
        }
        bool h16 = (lane & 16) != 0;
        float snd = h16 ? p[0] : p[1];
        float rcv = __shfl_xor_sync(m, snd, 16);
        float x = (h16 ? p[1] : p[0]) + rcv;
        snd = h16 ? p[2] : p[3];
        rcv = __shfl_xor_sync(m, snd, 16);
        float y = (h16 ? p[3] : p[2]) + rcv;
        bool h8 = (lane & 8) != 0;
        snd = h8 ? x : y;
        rcv = __shfl_xor_sync(m, snd, 8);
        float z = (h8 ? y : x) + rcv;
        z += __shfl_xor_sync(m, z, 4);
        z += __shfl_xor_sync(m, z, 2);
        z += __shfl_xor_sync(m, z, 1);
        if ((lane & 7) == 0) {
            int grp = lane >> 3;
            int off = (grp == 1) ? 2 : (grp == 2) ? 1 : (grp == 3) ? 3 : 0;
            dotres[q * 4 + off] = z;
        }
    }
    __syncthreads();

    // side warps: 0 = S, 1 = T, lane = history index h
    if (warp < 2) {
        int side = warp;
        int h = lane;
        bool act = h < H;
        float dsv = delta_s[si];
        float dtv = delta_t[di];
        float dh = act ? (side ? dt_[h] : ds_[h]) : 0.f;
        float nE = act ? dotres[(side ? 85 : 65) + h] : 0.f;
        float score = (side ? dotres[2] : dotres[1]) +
                      (act ? dotres[(side ? 33 : 13) + h] : 0.f);
        float sim;
        if (act) {
            float xv = expf(-dsv * dh) * score;   // ref uses ds for both sims
            sim = xv > 0.f ? xv : 0.2f * xv;
        } else sim = -1e30f;
        float mx = warpMax(sim);
        float ex = act ? expf(sim - mx) : 0.f;
        float sume = warpSum(ex);
        float att = ex / sume;
        float mask = act ? (side ? smT[h] : smS[h]) : 0.f;
        if (act) (side ? attmT : attmS)[h] = att * mask;
        float deltaX = side ? dtv : dsv;
        float ew = act ? expf(deltaX * dh) * att * mask : 0.f;
        if (act) (side ? ewT : ewS)[h] = ew;
        float A = warpSum(ew);
        float C = warpSum(ew * nE);
        float md = warpSum(act ? dh : 0.f) * (1.f / H);
        if (lane == 0) {
            scal[0 + side] = deltaX;
            scal[4 + side] = C;
            scal[6 + side] = A;
            scal[8 + side] = md;
        }
    }
    __syncthreads();

    // weighted vectors: u (att*mask) and v (ew) for each side
    {
        float* smf = (float*)vecs;
        float us = 0.f, vs = 0.f, ut = 0.f, vtv = 0.f;
        #pragma unroll 4
        for (int h = 0; h < H; h++) {
            float es = smf[(15 + h) * E + tid];
            float et = smf[(35 + h) * E + tid];
            us  = fmaf(attmS[h], es, us);
            vs  = fmaf(ewS[h],   es, vs);
            ut  = fmaf(attmT[h], et, ut);
            vtv = fmaf(ewT[h],   et, vtv);
        }
        smf[55 * E + tid] = us;
        smf[56 * E + tid] = ut;
        smf[57 * E + tid] = vs;
        smf[58 * E + tid] = vtv;
    }
    __syncthreads();

    // phase-2 dots: quads 27..30, one per warp
    {
        int q = 27 + warp;
        ushort4 t4 = ((const ushort4*)g_tasks)[q];
        float p[4];
        unsigned short tt[4] = {t4.x, t4.y, t4.z, t4.w};
        #pragma unroll
        for (int k = 0; k < 4; k++) {
            int l = tt[k] >> 8, r = tt[k] & 255;
            F4U2 A, B;
            A.f4 = vt[l * 32 + lane];
            B.f4 = vt[r * 32 + lane];
            unsigned long long pr = mul2(A.u.lo, B.u.lo);
            pr = fma2(A.u.hi, B.u.hi, pr);
            p[k] = hadd2(pr);
        }
        bool h16 = (lane & 16) != 0;
        float snd = h16 ? p[0] : p[1];
        float rcv = __shfl_xor_sync(m, snd, 16);
        float x = (h16 ? p[1] : p[0]) + rcv;
        snd = h16 ? p[2] : p[3];
        rcv = __shfl_xor_sync(m, snd, 16);
        float y = (h16 ? p[3] : p[2]) + rcv;
        bool h8 = (lane & 8) != 0;
        snd = h8 ? x : y;
        rcv = __shfl_xor_sync(m, snd, 8);
        float z = (h8 ? y : x) + rcv;
        z += __shfl_xor_sync(m, z, 4);
        z += __shfl_xor_sync(m, z, 2);
        z += __shfl_xor_sync(m, z, 1);
        if ((lane & 7) == 0) {
            int grp = lane >> 3;
            int off = (grp == 1) ? 2 : (grp == 2) ? 1 : (grp == 3) ? 3 : 0;
            dotres[q * 4 + off] = z;
        }
    }
    __syncthreads();

    // final scalar tail
    if (tid == 0) {
        float dsv = scal[0], dtv = scal[1];
        float C_S = scal[4], C_T = scal[5];
        float A_S = scal[6], A_T = scal[7];
        float fs = expf(-dsv * scal[8]);
        float ft = expf(-dtv * scal[9]);
        float gbv = gb[0];
        float ls = tanhf(fs * dotres[108] + gbv);
        float lt = tanhf(ft * dotres[109] + gbv);
        float mm = fmaxf(ls, lt);
        float egs = expf(ls - mm), egt = expf(lt - mm);
        float inv = 1.f / (egs + egt);
        float ga_s = egs * inv, ga_t = egt * inv;

        float np0 = dotres[53], np1 = dotres[54];
        float p_mu = np0 + np1 - 2.f * dotres[0];
        float psum_s = C_S + A_S * np1 - 2.f * dotres[110];
        float psum_t = C_T + A_T * np0 - 2.f * dotres[111];
        float plam = p_mu + ga_s * psum_s + ga_t * psum_t;
        float pos = fmaxf(dotres[0], 0.f);
        float pm1 = pos - 1.f;
        float pl = -logf(1.f / (1.f + expf(-plam)) + 1e-6f) * pm1 * pm1;

        float nsum = 0.f;
        #pragma unroll
        for (int n = 0; n < NEG; n++) {
            float nnd = dotres[55 + n], nns = dotres[60 + n];
            float asn = C_S - 2.f * dotres[112 + n] + nnd * A_S;
            float atn = C_T - 2.f * dotres[117 + n] + nns * A_T;
            float nls = (np0 + nnd - 2.f * dotres[3 + n]) + ga_s * asn;
            float nlt = (np1 + nns - 2.f * dotres[8 + n]) + ga_t * atn;
            float negs = fmaxf(dotres[3 + n], 0.f);
            float negt = fmaxf(dotres[8 + n], 0.f);
            nsum += -logf(1.f / (1.f + expf(nls)) + 1e-6f) * negs * negs;
            nsum += -logf(1.f / (1.f + expf(nlt)) + 1e-6f) * negt * negt;
        }
        g_pp[b] = pl;
        g_pn[b] = nsum;
        out[1 + b] = pos;
    }
}

// ---------------------------------------------------------------------------
// K3: deterministic loss reduction
// ---------------------------------------------------------------------------
__global__ void loss_kernel(float* __restrict__ out) {
    __shared__ float s1[256], s2[256];
    int t = threadIdx.x;
    float a = 0.f, c = 0.f;
    const float4* p1 = (const float4*)g_pp;
    const float4* p2 = (const float4*)g_pn;
    for (int i = t; i < BB / 4; i += 256) {
        float4 v = p1[i]; a += (v.x + v.y) + (v.z + v.w);
        float4 u = p2[i]; c += (u.x + u.y) + (u.z + u.w);
    }
    s1[t] = a; s2[t] = c;
    __syncthreads();
    for (int o = 128; o > 0; o >>= 1) {
        if (t < o) { s1[t] += s1[t + o]; s2[t] += s2[t + o]; }
        __syncthreads();
    }
    if (t == 0) out[0] = s1[0] / 4096.0f + s2[0] / (4096.0f * 5.0f);
}

// ---------------------------------------------------------------------------
extern "C" void kernel_launch(void* const* d_in, const int* in_sizes, int n_in,
                              void* d_out, int out_size) {
    const float* nf      = (const float*)d_in[0];
    const int*   src     = (const int*)  d_in[1];
    const int*   dst     = (const int*)  d_in[2];
    const float* etm     = (const float*)d_in[3];
    const int*   shn     = (const int*)  d_in[4];
    const int*   thn     = (const int*)  d_in[5];
    const float* shtimes = (const float*)d_in[6];
    const float* thtimes = (const float*)d_in[7];
    const float* smask   = (const float*)d_in[8];
    const float* tmask   = (const float*)d_in[9];
    const int*   nsrc    = (const int*)  d_in[10];
    const int*   ndst    = (const int*)  d_in[11];
    const float* W1      = (const float*)d_in[12];
    const float* b1      = (const float*)d_in[13];
    const float* W2      = (const float*)d_in[14];
    const float* b2      = (const float*)d_in[15];
    const float* W       = (const float*)d_in[16];
    const float* a       = (const float*)d_in[17];
    const float* dsp     = (const float*)d_in[18];
    const float* dtp     = (const float*)d_in[19];
    const float* gw      = (const float*)d_in[20];
    const float* gb      = (const float*)d_in[21];

    float* out = (float*)d_out;
    float* emb_out = out + 1 + BB;   // node_emb output region (4B-aligned only!)

    float* Hbuf;  cudaGetSymbolAddress((void**)&Hbuf, g_H);
    float* Ebuf;  cudaGetSymbolAddress((void**)&Ebuf, g_emb);

    precompute_kernel<<<1, 128>>>(W, a, gw);
    mlp1_kernel<<<740, 128>>>(nf, W1, b1, Hbuf);
    mlp2_kernel<<<1036, 128>>>(Hbuf, W2, b2, emb_out, Ebuf);
    batch_kernel<<<BB, 128>>>(src, dst, etm, shn, thn, shtimes, thtimes,
                              smask, tmask, nsrc, ndst, dsp, dtp, gb, Ebuf, out);
    loss_kernel<<<1, 256>>>(out);
}

// round 8
// speedup vs baseline: 2.9552x; 1.1296x over previous
#include <cuda_runtime.h>
#include <cuda_bf16.h>
#include <math.h>

// Problem constants
#define NNODES 200000
#define E 128
#define BB 4096
#define H 20
#define NEG 5
#define NTILE 1563     // ceil(200000/128)
#define NTASK 124
#define NVEC 55
#define NVEC2 59

// fused-MLP smem geometry (floats)
#define PAD_A  132
#define PAD_H  68
#define PAD_B1 72
#define PAD_B2 132
#define SM_FLOATS (128*PAD_A + 128*PAD_H + 128*PAD_B1 + 64*PAD_B2 + 192)
#define SMEM_FUSED (SM_FLOATS * 4)

// Scratch (device globals, allocation-free)
__device__ __align__(16) float g_Wa1[E];
__device__ __align__(16) float g_Wa2[E];
__device__ __align__(16) float g_Wgw[E];
__device__ float g_pp[BB];
__device__ float g_pn[BB];
__device__ __align__(16) float g_emb[(size_t)NNODES * E];
__device__ __align__(8)  unsigned short g_tasks[NTASK];

// ---------------------------------------------------------------------------
// helpers
// ---------------------------------------------------------------------------
__device__ __forceinline__ unsigned long long mul2(unsigned long long a, unsigned long long b) {
    unsigned long long d;
    asm("mul.rn.f32x2 %0, %1, %2;" : "=l"(d) : "l"(a), "l"(b));
    return d;
}
__device__ __forceinline__ unsigned long long fma2(unsigned long long a, unsigned long long b,
                                                   unsigned long long c) {
    unsigned long long d;
    asm("fma.rn.f32x2 %0, %1, %2, %3;" : "=l"(d) : "l"(a), "l"(b), "l"(c));
    return d;
}
__device__ __forceinline__ float hadd2(unsigned long long v) {
    return __uint_as_float((unsigned)(v & 0xffffffffull)) +
           __uint_as_float((unsigned)(v >> 32));
}
union F4U2 { float4 f4; struct { unsigned long long lo, hi; } u; };

__device__ __forceinline__ float warpSum(float v) {
    #pragma unroll
    for (int o = 16; o > 0; o >>= 1) v += __shfl_xor_sync(0xffffffffu, v, o);
    return v;
}
__device__ __forceinline__ float warpMax(float v) {
    #pragma unroll
    for (int o = 16; o > 0; o >>= 1) v = fmaxf(v, __shfl_xor_sync(0xffffffffu, v, o));
    return v;
}

// tf32 split: x = hi + lo, both tf32-representable
__device__ __forceinline__ void splitf(float x, unsigned& h, unsigned& l) {
    asm("cvt.rna.tf32.f32 %0, %1;" : "=r"(h) : "f"(x));
    float r = x - __uint_as_float(h);
    asm("cvt.rna.tf32.f32 %0, %1;" : "=r"(l) : "f"(r));
}

// D += A * B (m16n8k8 tf32, fp32 accum) — baseline PTX, sm_80+
__device__ __forceinline__ void mma8(float* d, const unsigned* a, unsigned b0, unsigned b1) {
    asm volatile("mma.sync.aligned.m16n8k8.row.col.f32.tf32.tf32.f32 "
        "{%0,%1,%2,%3}, {%4,%5,%6,%7}, {%8,%9}, {%0,%1,%2,%3};"
        : "+f"(d[0]), "+f"(d[1]), "+f"(d[2]), "+f"(d[3])
        : "r"(a[0]), "r"(a[1]), "r"(a[2]), "r"(a[3]), "r"(b0), "r"(b1));
}

// ---------------------------------------------------------------------------
// Fused MLP: emb = relu(X@W1+b1)@W2+b2 via mma.sync tf32 (3xTF32 split)
// 256 threads, warp w owns rows [w*16, w*16+16) of the 128-row tile.
// ---------------------------------------------------------------------------
__global__ void __launch_bounds__(256)
fused_mlp_kernel(const float* __restrict__ nf,
                 const float* __restrict__ W1, const float* __restrict__ b1,
                 const float* __restrict__ W2, const float* __restrict__ b2,
                 float* __restrict__ emb_out, float* __restrict__ emb_al) {
    extern __shared__ float sm[];
    float* sX  = sm;                       // [128][132]
    float* sH  = sX + 128 * PAD_A;         // [128][68]
    float* sB1 = sH + 128 * PAD_H;         // [128][72]  W1 (k-major, n padded)
    float* sB2 = sB1 + 128 * PAD_B1;       // [64][132]  W2 (k-major, n padded)
    float* b1s = sB2 + 64 * PAD_B2;        // 64
    float* b2s = b1s + 64;                 // 128

    int tid = threadIdx.x, wid = tid >> 5, lane = tid & 31;
    int gq = lane >> 2, tg = lane & 3;     // quad row-group, thread-in-group
    int m0 = wid * 16;

    // one-time weight staging
    for (int i = tid; i < 128 * 64; i += 256) {
        int k = i >> 6, n = i & 63;
        sB1[k * PAD_B1 + n] = (n < 60) ? W1[k * 60 + n] : 0.f;
    }
    for (int i = tid; i < 64 * 128; i += 256) {
        int k = i >> 7, n = i & 127;
        sB2[k * PAD_B2 + n] = (k < 60) ? W2[k * 128 + n] : 0.f;
    }
    if (tid < 64) b1s[tid] = (tid < 60) ? b1[tid] : 0.f;
    if (tid >= 64 && tid < 192) b2s[tid - 64] = b2[tid - 64];
    __syncthreads();

    for (int tile = blockIdx.x; tile < NTILE; tile += gridDim.x) {
        size_t base = (size_t)tile * 128;

        // stage X tile (zero-padded rows past NNODES)
        #pragma unroll
        for (int i = 0; i < 16; i++) {
            int idx = tid + i * 256;           // float4 index, 0..4095
            int r = idx >> 5, c = idx & 31;
            float4 v = make_float4(0.f, 0.f, 0.f, 0.f);
            if (base + r < NNODES) v = ((const float4*)(nf + (base + r) * 128))[c];
            *(float4*)&sX[r * PAD_A + c * 4] = v;
        }
        __syncthreads();

        // ---- layer 1: D1[16x64 per warp] = X(16x128) @ W1(128x64) ----
        float acc1[8][4];
        #pragma unroll
        for (int nt = 0; nt < 8; nt++)
            #pragma unroll
            for (int j = 0; j < 4; j++) acc1[nt][j] = 0.f;

        #pragma unroll 4
        for (int kk = 0; kk < 16; kk++) {
            int k0 = kk * 8;
            unsigned ah[4], al[4];
            splitf(sX[(m0 + gq)     * PAD_A + k0 + tg],     ah[0], al[0]);
            splitf(sX[(m0 + gq + 8) * PAD_A + k0 + tg],     ah[1], al[1]);
            splitf(sX[(m0 + gq)     * PAD_A + k0 + tg + 4], ah[2], al[2]);
            splitf(sX[(m0 + gq + 8) * PAD_A + k0 + tg + 4], ah[3], al[3]);
            #pragma unroll
            for (int nt = 0; nt < 8; nt++) {
                unsigned bh0, bl0, bh1, bl1;
                splitf(sB1[(k0 + tg)     * PAD_B1 + nt * 8 + gq], bh0, bl0);
                splitf(sB1[(k0 + tg + 4) * PAD_B1 + nt * 8 + gq], bh1, bl1);
                mma8(acc1[nt], ah, bh0, bh1);
                mma8(acc1[nt], al, bh0, bh1);
                mma8(acc1[nt], ah, bl0, bl1);
            }
        }

        // epilogue 1: H = relu(D1 + b1) -> smem
        #pragma unroll
        for (int nt = 0; nt < 8; nt++) {
            int c0 = nt * 8 + tg * 2;
            float h00 = fmaxf(acc1[nt][0] + b1s[c0],     0.f);
            float h01 = fmaxf(acc1[nt][1] + b1s[c0 + 1], 0.f);
            float h10 = fmaxf(acc1[nt][2] + b1s[c0],     0.f);
            float h11 = fmaxf(acc1[nt][3] + b1s[c0 + 1], 0.f);
            *(float2*)&sH[(m0 + gq)     * PAD_H + c0] = make_float2(h00, h01);
            *(float2*)&sH[(m0 + gq + 8) * PAD_H + c0] = make_float2(h10, h11);
        }
        __syncwarp();   // sH rows are private to this warp; no cross-warp reads

        // ---- layer 2: D2[16x128 per warp] = H(16x64) @ W2(64x128) ----
        float acc2[16][4];
        #pragma unroll
        for (int nt = 0; nt < 16; nt++)
            #pragma unroll
            for (int j = 0; j < 4; j++) acc2[nt][j] = 0.f;

        #pragma unroll 2
        for (int kk = 0; kk < 8; kk++) {
            int k0 = kk * 8;
            unsigned ah[4], al[4];
            splitf(sH[(m0 + gq)     * PAD_H + k0 + tg],     ah[0], al[0]);
            splitf(sH[(m0 + gq + 8) * PAD_H + k0 + tg],     ah[1], al[1]);
            splitf(sH[(m0 + gq)     * PAD_H + k0 + tg + 4], ah[2], al[2]);
            splitf(sH[(m0 + gq + 8) * PAD_H + k0 + tg + 4], ah[3], al[3]);
            #pragma unroll
            for (int nt = 0; nt < 16; nt++) {
                unsigned bh0, bl0, bh1, bl1;
                splitf(sB2[(k0 + tg)     * PAD_B2 + nt * 8 + gq], bh0, bl0);
                splitf(sB2[(k0 + tg + 4) * PAD_B2 + nt * 8 + gq], bh1, bl1);
                mma8(acc2[nt], ah, bh0, bh1);
                mma8(acc2[nt], al, bh0, bh1);
                mma8(acc2[nt], ah, bl0, bl1);
            }
        }

        // epilogue 2: emb = D2 + b2 -> both gmem buffers
        {
            int r0 = m0 + gq, r1 = r0 + 8;
            bool v0 = (base + r0) < NNODES, v1 = (base + r1) < NNODES;
            #pragma unroll
            for (int nt = 0; nt < 16; nt++) {
                int c0 = nt * 8 + tg * 2;
                float o00 = acc2[nt][0] + b2s[c0];
                float o01 = acc2[nt][1] + b2s[c0 + 1];
                float o10 = acc2[nt][2] + b2s[c0];
                float o11 = acc2[nt][3] + b2s[c0 + 1];
                if (v0) {
                    *(float2*)&emb_al[(base + r0) * 128 + c0] = make_float2(o00, o01);
                    emb_out[(base + r0) * 128 + c0]     = o00;
                    emb_out[(base + r0) * 128 + c0 + 1] = o01;
                }
                if (v1) {
                    *(float2*)&emb_al[(base + r1) * 128 + c0] = make_float2(o10, o11);
                    emb_out[(base + r1) * 128 + c0]     = o10;
                    emb_out[(base + r1) * 128 + c0 + 1] = o11;
                }
            }
        }
        __syncthreads();   // protect sX before next tile's staging
    }
}

// ---------------------------------------------------------------------------
// Task table (unchanged)
// ---------------------------------------------------------------------------
__device__ void taskDecode(int i, int& l, int& r) {
    if      (i == 0)  { l = 0; r = 1; }
    else if (i == 1)  { l = 0; r = 2; }
    else if (i == 2)  { l = 1; r = 2; }
    else if (i < 8)   { l = 0; r = 5 + (i - 3); }
    else if (i < 13)  { l = 1; r = 10 + (i - 8); }
    else if (i < 33)  { l = 15 + (i - 13); r = 3; }
    else if (i < 53)  { l = 35 + (i - 33); r = 3; }
    else if (i == 53) { l = 0; r = 0; }
    else if (i == 54) { l = 1; r = 1; }
    else if (i < 60)  { l = 5 + (i - 55); r = l; }
    else if (i < 65)  { l = 10 + (i - 60); r = l; }
    else if (i < 85)  { l = 15 + (i - 65); r = l; }
    else if (i < 105) { l = 35 + (i - 85); r = l; }
    else if (i < 108) { l = 0; r = 0; }
    else if (i == 108){ l = 55; r = 4; }
    else if (i == 109){ l = 56; r = 4; }
    else if (i == 110){ l = 57; r = 1; }
    else if (i == 111){ l = 58; r = 0; }
    else if (i < 117) { l = 57; r = 5 + (i - 112); }
    else if (i < 122) { l = 58; r = 10 + (i - 117); }
    else              { l = 0; r = 0; }
}

__global__ void precompute_kernel(const float* __restrict__ W,
                                  const float* __restrict__ a,
                                  const float* __restrict__ gw) {
    int tid = threadIdx.x;
    int warp = tid >> 5, lane = tid & 31;
    for (int row = warp; row < E; row += 4) {
        const float* wr = W + row * E;
        float s1 = 0.f, s2 = 0.f, s3 = 0.f;
        #pragma unroll
        for (int i = 0; i < 4; i++) {
            float wv = wr[lane + 32 * i];
            s1 = fmaf(wv, a[lane + 32 * i], s1);
            s2 = fmaf(wv, a[E + lane + 32 * i], s2);
            s3 = fmaf(wv, gw[lane + 32 * i], s3);
        }
        s1 = warpSum(s1); s2 = warpSum(s2); s3 = warpSum(s3);
        if (lane == 0) { g_Wa1[row] = s1; g_Wa2[row] = s2; g_Wgw[row] = s3; }
    }
    for (int i = tid; i < NTASK; i += 128) {
        int l, r;
        taskDecode(i, l, r);
        g_tasks[i] = (unsigned short)((l << 8) | r);
    }
}

// ---------------------------------------------------------------------------
// K2: batch kernel (unchanged from R6)
// ---------------------------------------------------------------------------
__global__ void __launch_bounds__(128)
batch_kernel(const int* __restrict__ src, const int* __restrict__ dst,
             const float* __restrict__ e_times,
             const int* __restrict__ shn, const int* __restrict__ thn,
             const float* __restrict__ s_h_times, const float* __restrict__ t_h_times,
             const float* __restrict__ s_mask, const float* __restrict__ t_mask,
             const int* __restrict__ nsrc, const int* __restrict__ ndst,
             const float* __restrict__ delta_s, const float* __restrict__ delta_t,
             const float* __restrict__ gb,
             const float* __restrict__ emb,
             float* __restrict__ out) {
    __shared__ float4 vecs[NVEC2][32];
    __shared__ float dotres[NTASK];
    __shared__ float ds_[H], dt_[H], smS[H], smT[H];
    __shared__ float attmS[H], attmT[H], ewS[H], ewT[H];
    __shared__ float scal[12];

    int b = blockIdx.x;
    int tid = threadIdx.x, warp = tid >> 5, lane = tid & 31;
    int si = src[b], di = dst[b];

    for (int v = warp; v < NVEC; v += 4) {
        const float* s;
        if      (v == 0) s = emb + (size_t)si * E;
        else if (v == 1) s = emb + (size_t)di * E;
        else if (v == 2) s = g_Wa1;
        else if (v == 3) s = g_Wa2;
        else if (v == 4) s = g_Wgw;
        else if (v < 10) s = emb + (size_t)ndst[b * NEG + (v - 5)] * E;
        else if (v < 15) s = emb + (size_t)nsrc[b * NEG + (v - 10)] * E;
        else if (v < 35) s = emb + (size_t)shn[b * H + (v - 15)] * E;
        else             s = emb + (size_t)thn[b * H + (v - 35)] * E;
        vecs[v][lane] = ((const float4*)s)[lane];
    }
    if (tid < H) {
        float et = e_times[b];
        ds_[tid] = fabsf(et - s_h_times[b * H + tid]);
        dt_[tid] = fabsf(et - t_h_times[b * H + tid]);
        smS[tid] = s_mask[b * H + tid];
        smT[tid] = t_mask[b * H + tid];
    }
    __syncthreads();

    const float4* vt = &vecs[0][0];
    unsigned m = 0xffffffffu;

    for (int q = warp; q < 27; q += 4) {
        ushort4 t4 = ((const ushort4*)g_tasks)[q];
        float p[4];
        unsigned short tt[4] = {t4.x, t4.y, t4.z, t4.w};
        #pragma unroll
        for (int k = 0; k < 4; k++) {
            int l = tt[k] >> 8, r = tt[k] & 255;
            F4U2 A, B;
            A.f4 = vt[l * 32 + lane];
            B.f4 = vt[r * 32 + lane];
            unsigned long long pr = mul2(A.u.lo, B.u.lo);
            pr = fma2(A.u.hi, B.u.hi, pr);
            p[k] = hadd2(pr);
        }
        bool h16 = (lane & 16) != 0;
        float snd = h16 ? p[0] : p[1];
        float rcv = __shfl_xor_sync(m, snd, 16);
        float x = (h16 ? p[1] : p[0]) + rcv;
        snd = h16 ? p[2] : p[3];
        rcv = __shfl_xor_sync(m, snd, 16);
        float y = (h16 ? p[3] : p[2]) + rcv;
        bool h8 = (lane & 8) != 0;
        snd = h8 ? x : y;
        rcv = __shfl_xor_sync(m, snd, 8);
        float z = (h8 ? y : x) + rcv;
        z += __shfl_xor_sync(m, z, 4);
        z += __shfl_xor_sync(m, z, 2);
        z += __shfl_xor_sync(m, z, 1);
        if ((lane & 7) == 0) {
            int grp = lane >> 3;
            int off = (grp == 1) ? 2 : (grp == 2) ? 1 : (grp == 3) ? 3 : 0;
            dotres[q * 4 + off] = z;
        }
    }
    __syncthreads();

    if (warp < 2) {
        int side = warp;
        int h = lane;
        bool act = h < H;
        float dsv = delta_s[si];
        float dtv = delta_t[di];
        float dh = act ? (side ? dt_[h] : ds_[h]) : 0.f;
        float nE = act ? dotres[(side ? 85 : 65) + h] : 0.f;
        float score = (side ? dotres[2] : dotres[1]) +
                      (act ? dotres[(side ? 33 : 13) + h] : 0.f);
        float sim;
        if (act) {
            float xv = expf(-dsv * dh) * score;
            sim = xv > 0.f ? xv : 0.2f * xv;
        } else sim = -1e30f;
        float mx = warpMax(sim);
        float ex = act ? expf(sim - mx) : 0.f;
        float sume = warpSum(ex);
        float att = ex / sume;
        float mask = act ? (side ? smT[h] : smS[h]) : 0.f;
        if (act) (side ? attmT : attmS)[h] = att * mask;
        float deltaX = side ? dtv : dsv;
        float ew = act ? expf(deltaX * dh) * att * mask : 0.f;
        if (act) (side ? ewT : ewS)[h] = ew;
        float A = warpSum(ew);
        float C = warpSum(ew * nE);
        float md = warpSum(act ? dh : 0.f) * (1.f / H);
        if (lane == 0) {
            scal[0 + side] = deltaX;
            scal[4 + side] = C;
            scal[6 + side] = A;
            scal[8 + side] = md;
        }
    }
    __syncthreads();

    {
        float* smf = (float*)vecs;
        float us = 0.f, vs = 0.f, ut = 0.f, vtv = 0.f;
        #pragma unroll 4
        for (int h = 0; h < H; h++) {
            float es = smf[(15 + h) * E + tid];
            float et = smf[(35 + h) * E + tid];
            us  = fmaf(attmS[h], es, us);
            vs  = fmaf(ewS[h],   es, vs);
            ut  = fmaf(attmT[h], et, ut);
            vtv = fmaf(ewT[h],   et, vtv);
        }
        smf[55 * E + tid] = us;
        smf[56 * E + tid] = ut;
        smf[57 * E + tid] = vs;
        smf[58 * E + tid] = vtv;
    }
    __syncthreads();

    {
        int q = 27 + warp;
        ushort4 t4 = ((const ushort4*)g_tasks)[q];
        float p[4];
        unsigned short tt[4] = {t4.x, t4.y, t4.z, t4.w};
        #pragma unroll
        for (int k = 0; k < 4; k++) {
            int l = tt[k] >> 8, r = tt[k] & 255;
            F4U2 A, B;
            A.f4 = vt[l * 32 + lane];
            B.f4 = vt[r * 32 + lane];
            unsigned long long pr = mul2(A.u.lo, B.u.lo);
            pr = fma2(A.u.hi, B.u.hi, pr);
            p[k] = hadd2(pr);
        }
        bool h16 = (lane & 16) != 0;
        float snd = h16 ? p[0] : p[1];
        float rcv = __shfl_xor_sync(m, snd, 16);
        float x = (h16 ? p[1] : p[0]) + rcv;
        snd = h16 ? p[2] : p[3];
        rcv = __shfl_xor_sync(m, snd, 16);
        float y = (h16 ? p[3] : p[2]) + rcv;
        bool h8 = (lane & 8) != 0;
        snd = h8 ? x : y;
        rcv = __shfl_xor_sync(m, snd, 8);
        float z = (h8 ? y : x) + rcv;
        z += __shfl_xor_sync(m, z, 4);
        z += __shfl_xor_sync(m, z, 2);
        z += __shfl_xor_sync(m, z, 1);
        if ((lane & 7) == 0) {
            int grp = lane >> 3;
            int off = (grp == 1) ? 2 : (grp == 2) ? 1 : (grp == 3) ? 3 : 0;
            dotres[q * 4 + off] = z;
        }
    }
    __syncthreads();

    if (tid == 0) {
        float dsv = scal[0], dtv = scal[1];
        float C_S = scal[4], C_T = scal[5];
        float A_S = scal[6], A_T = scal[7];
        float fs = expf(-dsv * scal[8]);
        float ft = expf(-dtv * scal[9]);
        float gbv = gb[0];
        float ls = tanhf(fs * dotres[108] + gbv);
        float lt = tanhf(ft * dotres[109] + gbv);
        float mm = fmaxf(ls, lt);
        float egs = expf(ls - mm), egt = expf(lt - mm);
        float inv = 1.f / (egs + egt);
        float ga_s = egs * inv, ga_t = egt * inv;

        float np0 = dotres[53], np1 = dotres[54];
        float p_mu = np0 + np1 - 2.f * dotres[0];
        float psum_s = C_S + A_S * np1 - 2.f * dotres[110];
        float psum_t = C_T + A_T * np0 - 2.f * dotres[111];
        float plam = p_mu + ga_s * psum_s + ga_t * psum_t;
        float pos = fmaxf(dotres[0], 0.f);
        float pm1 = pos - 1.f;
        float pl = -logf(1.f / (1.f + expf(-plam)) + 1e-6f) * pm1 * pm1;

        float nsum = 0.f;
        #pragma unroll
        for (int n = 0; n < NEG; n++) {
            float nnd = dotres[55 + n], nns = dotres[60 + n];
            float asn = C_S - 2.f * dotres[112 + n] + nnd * A_S;
            float atn = C_T - 2.f * dotres[117 + n] + nns * A_T;
            float nls = (np0 + nnd - 2.f * dotres[3 + n]) + ga_s * asn;
            float nlt = (np1 + nns - 2.f * dotres[8 + n]) + ga_t * atn;
            float negs = fmaxf(dotres[3 + n], 0.f);
            float negt = fmaxf(dotres[8 + n], 0.f);
            nsum += -logf(1.f / (1.f + expf(nls)) + 1e-6f) * negs * negs;
            nsum += -logf(1.f / (1.f + expf(nlt)) + 1e-6f) * negt * negt;
        }
        g_pp[b] = pl;
        g_pn[b] = nsum;
        out[1 + b] = pos;
    }
}

// ---------------------------------------------------------------------------
// K3: deterministic loss reduction
// ---------------------------------------------------------------------------
__global__ void loss_kernel(float* __restrict__ out) {
    __shared__ float s1[256], s2[256];
    int t = threadIdx.x;
    float a = 0.f, c = 0.f;
    const float4* p1 = (const float4*)g_pp;
    const float4* p2 = (const float4*)g_pn;
    for (int i = t; i < BB / 4; i += 256) {
        float4 v = p1[i]; a += (v.x + v.y) + (v.z + v.w);
        float4 u = p2[i]; c += (u.x + u.y) + (u.z + u.w);
    }
    s1[t] = a; s2[t] = c;
    __syncthreads();
    for (int o = 128; o > 0; o >>= 1) {
        if (t < o) { s1[t] += s1[t + o]; s2[t] += s2[t + o]; }
        __syncthreads();
    }
    if (t == 0) out[0] = s1[0] / 4096.0f + s2[0] / (4096.0f * 5.0f);
}

// ---------------------------------------------------------------------------
extern "C" void kernel_launch(void* const* d_in, const int* in_sizes, int n_in,
                              void* d_out, int out_size) {
    const float* nf      = (const float*)d_in[0];
    const int*   src     = (const int*)  d_in[1];
    const int*   dst     = (const int*)  d_in[2];
    const float* etm     = (const float*)d_in[3];
    const int*   shn     = (const int*)  d_in[4];
    const int*   thn     = (const int*)  d_in[5];
    const float* shtimes = (const float*)d_in[6];
    const float* thtimes = (const float*)d_in[7];
    const float* smask   = (const float*)d_in[8];
    const float* tmask   = (const float*)d_in[9];
    const int*   nsrc    = (const int*)  d_in[10];
    const int*   ndst    = (const int*)  d_in[11];
    const float* W1      = (const float*)d_in[12];
    const float* b1      = (const float*)d_in[13];
    const float* W2      = (const float*)d_in[14];
    const float* b2      = (const float*)d_in[15];
    const float* W       = (const float*)d_in[16];
    const float* a       = (const float*)d_in[17];
    const float* dsp     = (const float*)d_in[18];
    const float* dtp     = (const float*)d_in[19];
    const float* gw      = (const float*)d_in[20];
    const float* gb      = (const float*)d_in[21];

    float* out = (float*)d_out;
    float* emb_out = out + 1 + BB;   // 4B-aligned only

    float* Ebuf;  cudaGetSymbolAddress((void**)&Ebuf, g_emb);

    cudaFuncSetAttribute(fused_mlp_kernel,
                         cudaFuncAttributeMaxDynamicSharedMemorySize, SMEM_FUSED);

    precompute_kernel<<<1, 128>>>(W, a, gw);
    fused_mlp_kernel<<<148, 256, SMEM_FUSED>>>(nf, W1, b1, W2, b2, emb_out, Ebuf);
    batch_kernel<<<BB, 128>>>(src, dst, etm, shn, thn, shtimes, thtimes,
                              smask, tmask, nsrc, ndst, dsp, dtp, gb, Ebuf, out);
    loss_kernel<<<1, 256>>>(out);
}